// round 1
// baseline (speedup 1.0000x reference)
#include <cuda_runtime.h>
#include <math.h>

// ---------------- problem constants ----------------
constexpr int kT   = 1024;
constexpr int kH   = 2048;
constexpr int kNH  = 16;
constexpr int kNKV = 4;
constexpr int kHD  = 128;
constexpr int kE   = 8;
constexpr int kI   = 768;
constexpr int kQKV = kNH*kHD + 2*kNKV*kHD;   // 3072
constexpr float kEPS = 1e-6f;
constexpr float kScale = 0.08838834764831845f; // 128^-0.5

constexpr int kSlots = 2560;   // 2*T + 8*64 padding headroom, multiple of 64
constexpr int kTiles = kSlots / 64; // 40

// ---------------- scratch (device globals; no allocation allowed) ----------------
__device__ float g_h1[kT*kH];            // ln1 output
__device__ float g_qkv[kT*kQKV];         // qkv (q/k normed+roped in place)
__device__ float g_scores[(size_t)kNH*kT*kT]; // 64MB attention matrix
__device__ float g_attn[kT*kH];          // attention output pre o-proj
__device__ float g_h2[kT*kH];            // ln2 output
__device__ float g_gu[(size_t)kSlots*2*kI];   // gate_up per slot
__device__ float g_act[(size_t)kSlots*kI];    // silu(g)*u per slot
__device__ float g_ds[(size_t)kSlots*kH];     // down output per slot
__device__ int   g_tok[kSlots];          // token id per slot (grouped/padded by expert), -1 = pad
__device__ float g_wt[kSlots];           // routing weight per slot
__device__ int   g_slot_of[kT*2];        // token -> its two slots
__device__ int   g_topi[kT*2];
__device__ float g_topw[kT*2];
__device__ int   g_cnt[kE];
__device__ int   g_cursor[kE];
__device__ int   g_tile_e[kTiles];
__device__ int   g_ntiles;

// ---------------- fused add + RMSNorm ----------------
__global__ void add_rms_kernel(const float* __restrict__ x, const float* __restrict__ r,
                               const float* __restrict__ w, float* __restrict__ res_out,
                               float* __restrict__ h_out) {
    const int t = blockIdx.x, tid = threadIdx.x;
    const float* xp = x + (size_t)t*kH;
    const float* rp = r ? r + (size_t)t*kH : nullptr;
    float v[8]; float ss = 0.f;
    #pragma unroll
    for (int i = 0; i < 8; i++) {
        int idx = tid + i*256;
        float val = xp[idx];
        if (rp) val += rp[idx];
        v[i] = val; ss += val*val;
    }
    __shared__ float sh[256];
    sh[tid] = ss; __syncthreads();
    for (int s = 128; s > 0; s >>= 1) { if (tid < s) sh[tid] += sh[tid+s]; __syncthreads(); }
    float scale = rsqrtf(sh[0]/(float)kH + kEPS);
    #pragma unroll
    for (int i = 0; i < 8; i++) {
        int idx = tid + i*256;
        if (res_out) res_out[(size_t)t*kH + idx] = v[i];
        h_out[(size_t)t*kH + idx] = v[i]*scale*w[idx];
    }
}

// ---------------- GEMM tile helpers (64x64 tile, 256 thr, 4x4/thr) ----------------
__device__ __forceinline__ void tile_loop_plain(const float* __restrict__ A, int lda,
                                                const float* __restrict__ B, int ldb,
                                                int Kdim, float acc[4][4]) {
    __shared__ float As[16][65];
    __shared__ float Bs[16][64];
    const int tid = threadIdx.x;
    const int ty = tid >> 4, tx = tid & 15;
    for (int kk = 0; kk < Kdim; kk += 16) {
        #pragma unroll
        for (int q = 0; q < 4; q++) {
            int e = tid + q*256;
            int m = e >> 4, k = e & 15;
            As[k][m] = A[(size_t)m*lda + kk + k];
        }
        #pragma unroll
        for (int q = 0; q < 4; q++) {
            int e = tid + q*256;
            int kb = e >> 6, n = e & 63;
            Bs[kb][n] = B[(size_t)(kk+kb)*ldb + n];
        }
        __syncthreads();
        #pragma unroll
        for (int k = 0; k < 16; k++) {
            float a[4], b[4];
            #pragma unroll
            for (int i = 0; i < 4; i++) a[i] = As[k][ty*4+i];
            #pragma unroll
            for (int j = 0; j < 4; j++) b[j] = Bs[k][tx*4+j];
            #pragma unroll
            for (int i = 0; i < 4; i++)
                #pragma unroll
                for (int j = 0; j < 4; j++)
                    acc[i][j] = fmaf(a[i], b[j], acc[i][j]);
        }
        __syncthreads();
    }
}

// B supplied transposed: Bt[n][k]  (used for Q*K^T)
__device__ __forceinline__ void tile_loop_tt(const float* __restrict__ A, int lda,
                                             const float* __restrict__ Bt, int ldbt,
                                             int Kdim, float acc[4][4]) {
    __shared__ float As[16][65];
    __shared__ float Bs[16][65];
    const int tid = threadIdx.x;
    const int ty = tid >> 4, tx = tid & 15;
    for (int kk = 0; kk < Kdim; kk += 16) {
        #pragma unroll
        for (int q = 0; q < 4; q++) {
            int e = tid + q*256;
            int m = e >> 4, k = e & 15;
            As[k][m] = A[(size_t)m*lda + kk + k];
            Bs[k][m] = Bt[(size_t)m*ldbt + kk + k];
        }
        __syncthreads();
        #pragma unroll
        for (int k = 0; k < 16; k++) {
            float a[4], b[4];
            #pragma unroll
            for (int i = 0; i < 4; i++) a[i] = As[k][ty*4+i];
            #pragma unroll
            for (int j = 0; j < 4; j++) b[j] = Bs[k][tx*4+j];
            #pragma unroll
            for (int i = 0; i < 4; i++)
                #pragma unroll
                for (int j = 0; j < 4; j++)
                    acc[i][j] = fmaf(a[i], b[j], acc[i][j]);
        }
        __syncthreads();
    }
}

// gathered-row A variant (MoE): A row m comes from token rows[m] (-1 => zeros)
__device__ __forceinline__ void tile_loop_gather(const float* __restrict__ Abase, int lda,
                                                 const int* __restrict__ toks,
                                                 const float* __restrict__ B, int ldb,
                                                 int Kdim, float acc[4][4]) {
    __shared__ float As[16][65];
    __shared__ float Bs[16][64];
    __shared__ int rows[64];
    const int tid = threadIdx.x;
    const int ty = tid >> 4, tx = tid & 15;
    if (tid < 64) rows[tid] = toks[tid];
    __syncthreads();
    for (int kk = 0; kk < Kdim; kk += 16) {
        #pragma unroll
        for (int q = 0; q < 4; q++) {
            int e = tid + q*256;
            int m = e >> 4, k = e & 15;
            int rt = rows[m];
            As[k][m] = (rt >= 0) ? Abase[(size_t)rt*lda + kk + k] : 0.f;
        }
        #pragma unroll
        for (int q = 0; q < 4; q++) {
            int e = tid + q*256;
            int kb = e >> 6, n = e & 63;
            Bs[kb][n] = B[(size_t)(kk+kb)*ldb + n];
        }
        __syncthreads();
        #pragma unroll
        for (int k = 0; k < 16; k++) {
            float a[4], b[4];
            #pragma unroll
            for (int i = 0; i < 4; i++) a[i] = As[k][ty*4+i];
            #pragma unroll
            for (int j = 0; j < 4; j++) b[j] = Bs[k][tx*4+j];
            #pragma unroll
            for (int i = 0; i < 4; i++)
                #pragma unroll
                for (int j = 0; j < 4; j++)
                    acc[i][j] = fmaf(a[i], b[j], acc[i][j]);
        }
        __syncthreads();
    }
}

// ---------------- generic GEMM (optional fused residual add) ----------------
__global__ void gemm_plain_kernel(const float* __restrict__ A, int lda,
                                  const float* __restrict__ B, int ldb,
                                  float* __restrict__ C, int ldc, int Kdim,
                                  const float* __restrict__ addsrc) {
    const int row0 = blockIdx.x*64, col0 = blockIdx.y*64;
    float acc[4][4] = {};
    tile_loop_plain(A + (size_t)row0*lda, lda, B + col0, ldb, Kdim, acc);
    const int ty = threadIdx.x >> 4, tx = threadIdx.x & 15;
    #pragma unroll
    for (int i = 0; i < 4; i++) {
        int m = row0 + ty*4 + i;
        #pragma unroll
        for (int j = 0; j < 4; j++) {
            int n = col0 + tx*4 + j;
            float v = acc[i][j];
            if (addsrc) v += addsrc[(size_t)m*ldc + n];
            C[(size_t)m*ldc + n] = v;
        }
    }
}

// ---------------- QK-RMSNorm + RoPE (in place on g_qkv) ----------------
__global__ void rope_kernel(const int* __restrict__ positions,
                            const float* __restrict__ q_norm_w,
                            const float* __restrict__ k_norm_w) {
    const int t = blockIdx.x, hh = blockIdx.y, lane = threadIdx.x; // 128 threads
    float* ptr = g_qkv + (size_t)t*kQKV + (hh < kNH ? hh*kHD : kNH*kHD + (hh-kNH)*kHD);
    const float* nw = (hh < kNH) ? q_norm_w : k_norm_w;
    float v = ptr[lane];
    __shared__ float sred[128];
    sred[lane] = v*v; __syncthreads();
    for (int s = 64; s > 0; s >>= 1) { if (lane < s) sred[lane] += sred[lane+s]; __syncthreads(); }
    float scale = rsqrtf(sred[0]/(float)kHD + kEPS);
    float xn = v*scale*nw[lane];
    __shared__ float sh[128];
    sh[lane] = xn; __syncthreads();
    int j = lane & 63;
    double inv = exp(-(double)j/64.0 * log(1.0e6));
    double ang = (double)positions[t] * inv;
    float c = (float)cos(ang), s = (float)sin(ang);
    float outv;
    if (lane < 64) outv = sh[lane]*c - sh[lane+64]*s;
    else           outv = sh[lane]*c + sh[lane-64]*s;
    ptr[lane] = outv;
}

// ---------------- attention scores: S = scale * Q K^T, causal mask ----------------
__global__ void scores_kernel() {
    const int qt = blockIdx.x, kt = blockIdx.y, h = blockIdx.z;
    if (kt*64 > qt*64 + 63) return;   // entirely above diagonal
    const float* Q  = g_qkv + (size_t)qt*64*kQKV + h*kHD;
    const float* Kp = g_qkv + (size_t)kt*64*kQKV + kNH*kHD + (h >> 2)*kHD;
    float acc[4][4] = {};
    tile_loop_tt(Q, kQKV, Kp, kQKV, kHD, acc);
    const int ty = threadIdx.x >> 4, tx = threadIdx.x & 15;
    #pragma unroll
    for (int i = 0; i < 4; i++) {
        int qi = qt*64 + ty*4 + i;
        #pragma unroll
        for (int j = 0; j < 4; j++) {
            int ki = kt*64 + tx*4 + j;
            float v = acc[i][j]*kScale;
            if (ki > qi) v = -1e9f;
            g_scores[((size_t)h*kT + qi)*kT + ki] = v;
        }
    }
}

// ---------------- row softmax (causal; zeros beyond diagonal) ----------------
__global__ void softmax_kernel() {
    const int q = blockIdx.x, h = blockIdx.y, tid = threadIdx.x;
    float* row = g_scores + ((size_t)h*kT + q)*kT;
    __shared__ float sh[256];
    float lmax = -3.4e38f;
    for (int k = tid; k <= q; k += 256) lmax = fmaxf(lmax, row[k]);
    sh[tid] = lmax; __syncthreads();
    for (int s = 128; s > 0; s >>= 1) { if (tid < s) sh[tid] = fmaxf(sh[tid], sh[tid+s]); __syncthreads(); }
    float m = sh[0]; __syncthreads();
    float lsum = 0.f;
    for (int k = tid; k <= q; k += 256) { float e = __expf(row[k]-m); row[k] = e; lsum += e; }
    sh[tid] = lsum; __syncthreads();
    for (int s = 128; s > 0; s >>= 1) { if (tid < s) sh[tid] += sh[tid+s]; __syncthreads(); }
    float inv = 1.f/sh[0];
    for (int k = tid; k < kT; k += 256) row[k] = (k <= q) ? row[k]*inv : 0.f;
}

// ---------------- PV: O_h = P V_h ----------------
__global__ void pv_kernel() {
    const int qt = blockIdx.x, nt = blockIdx.y, h = blockIdx.z;
    const int row0 = qt*64, col0 = nt*64;
    const float* A = g_scores + ((size_t)h*kT + row0)*kT;
    const float* B = g_qkv + kNH*kHD + kNKV*kHD + (h >> 2)*kHD + col0;
    float acc[4][4] = {};
    tile_loop_plain(A, kT, B, kQKV, kT, acc);
    const int ty = threadIdx.x >> 4, tx = threadIdx.x & 15;
    #pragma unroll
    for (int i = 0; i < 4; i++) {
        int m = row0 + ty*4 + i;
        #pragma unroll
        for (int j = 0; j < 4; j++) {
            int n = col0 + tx*4 + j;
            g_attn[(size_t)m*kH + h*kHD + n] = acc[i][j];
        }
    }
}

// ---------------- router: logits -> softmax -> top2 (renormed) ----------------
__global__ void router_kernel(const float* __restrict__ gate_w) {
    const int t = blockIdx.x, tid = threadIdx.x;
    const float* hp = g_h2 + (size_t)t*kH;
    float acc[kE] = {};
    for (int k = tid; k < kH; k += 256) {
        float hv = hp[k];
        const float* gw = gate_w + (size_t)k*kE;
        #pragma unroll
        for (int e = 0; e < kE; e++) acc[e] += hv*gw[e];
    }
    __shared__ float sh[kE][256];
    #pragma unroll
    for (int e = 0; e < kE; e++) sh[e][tid] = acc[e];
    __syncthreads();
    for (int s = 128; s > 0; s >>= 1) {
        if (tid < s) {
            #pragma unroll
            for (int e = 0; e < kE; e++) sh[e][tid] += sh[e][tid+s];
        }
        __syncthreads();
    }
    if (tid == 0) {
        float l[kE], mx = -3.4e38f;
        #pragma unroll
        for (int e = 0; e < kE; e++) { l[e] = sh[e][0]; mx = fmaxf(mx, l[e]); }
        float sum = 0.f;
        #pragma unroll
        for (int e = 0; e < kE; e++) { l[e] = __expf(l[e]-mx); sum += l[e]; }
        float isum = 1.f/sum;
        float best = -1.f, second = -1.f; int bi = 0, si = 0;
        #pragma unroll
        for (int e = 0; e < kE; e++) {
            float p = l[e]*isum;
            if (p > best) { second = best; si = bi; best = p; bi = e; }
            else if (p > second) { second = p; si = e; }
        }
        float denom = 1.f/(best + second);
        g_topi[t*2]   = bi; g_topw[t*2]   = best*denom;
        g_topi[t*2+1] = si; g_topw[t*2+1] = second*denom;
        atomicAdd(&g_cnt[bi], 1);
        atomicAdd(&g_cnt[si], 1);
    }
}

__global__ void moe_init_kernel() {
    int i = blockIdx.x*256 + threadIdx.x;
    if (i < kE) { g_cnt[i] = 0; }
    if (i < kSlots) g_tok[i] = -1;
}

__global__ void moe_setup_kernel() {
    int off = 0, tile = 0;
    for (int e = 0; e < kE; e++) {
        g_cursor[e] = off;
        int seg = ((g_cnt[e] + 63)/64)*64;
        for (int i = 0; i < seg/64; i++) g_tile_e[tile++] = e;
        off += seg;
    }
    g_ntiles = tile;
}

__global__ void moe_scatter_kernel() {
    int t = blockIdx.x*256 + threadIdx.x;
    if (t >= kT) return;
    #pragma unroll
    for (int k = 0; k < 2; k++) {
        int e = g_topi[t*2+k];
        int pos = atomicAdd(&g_cursor[e], 1);
        g_tok[pos] = t;
        g_wt[pos]  = g_topw[t*2+k];
        g_slot_of[t*2+k] = pos;
    }
}

// ---------------- MoE GEMM 1: gate_up, gathered rows ----------------
__global__ void moe_gu_kernel(const float* __restrict__ w_gate_up) {
    const int tile = blockIdx.x;
    if (tile >= g_ntiles) return;
    const int e = g_tile_e[tile];
    const int col0 = blockIdx.y*64;
    const float* B = w_gate_up + (size_t)e*kH*2*kI + col0;
    float acc[4][4] = {};
    tile_loop_gather(g_h2, kH, g_tok + tile*64, B, 2*kI, kH, acc);
    const int ty = threadIdx.x >> 4, tx = threadIdx.x & 15;
    #pragma unroll
    for (int i = 0; i < 4; i++) {
        int slot = tile*64 + ty*4 + i;
        #pragma unroll
        for (int j = 0; j < 4; j++)
            g_gu[(size_t)slot*2*kI + col0 + tx*4 + j] = acc[i][j];
    }
}

__global__ void silu_kernel() {
    int idx = blockIdx.x*256 + threadIdx.x;
    int slot = idx / kI, j = idx % kI;
    if (slot >= g_ntiles*64) return;
    float g = g_gu[(size_t)slot*2*kI + j];
    float u = g_gu[(size_t)slot*2*kI + kI + j];
    g_act[idx] = (g / (1.f + __expf(-g))) * u;
}

// ---------------- MoE GEMM 2: down ----------------
__global__ void moe_down_kernel(const float* __restrict__ w_down) {
    const int tile = blockIdx.x;
    if (tile >= g_ntiles) return;
    const int e = g_tile_e[tile];
    const int col0 = blockIdx.y*64;
    const float* A = g_act + (size_t)tile*64*kI;
    const float* B = w_down + (size_t)e*kI*kH + col0;
    float acc[4][4] = {};
    tile_loop_plain(A, kI, B, kH, kI, acc);
    const int ty = threadIdx.x >> 4, tx = threadIdx.x & 15;
    #pragma unroll
    for (int i = 0; i < 4; i++) {
        int slot = tile*64 + ty*4 + i;
        #pragma unroll
        for (int j = 0; j < 4; j++)
            g_ds[(size_t)slot*kH + col0 + tx*4 + j] = acc[i][j];
    }
}

__global__ void combine_kernel(float* __restrict__ out) {
    const int t = blockIdx.x;
    const int s0 = g_slot_of[t*2], s1 = g_slot_of[t*2+1];
    const float w0 = g_wt[s0], w1 = g_wt[s1];
    for (int j = threadIdx.x; j < kH; j += 256)
        out[(size_t)t*kH + j] = w0*g_ds[(size_t)s0*kH + j] + w1*g_ds[(size_t)s1*kH + j];
}

// ---------------- launcher ----------------
extern "C" void kernel_launch(void* const* d_in, const int* in_sizes, int n_in,
                              void* d_out, int out_size) {
    const int*   positions = (const int*)  d_in[0];
    const float* hidden    = (const float*)d_in[1];
    const float* residual  = (const float*)d_in[2];
    const float* w_qkv     = (const float*)d_in[3];
    const float* w_o       = (const float*)d_in[4];
    const float* q_norm_w  = (const float*)d_in[5];
    const float* k_norm_w  = (const float*)d_in[6];
    const float* ln1_w     = (const float*)d_in[7];
    const float* ln2_w     = (const float*)d_in[8];
    const float* gate_w    = (const float*)d_in[9];
    const float* w_gate_up = (const float*)d_in[10];
    const float* w_down    = (const float*)d_in[11];
    float* out = (float*)d_out;
    float* res = out + (size_t)kT*kH;

    float* d_h1;   cudaGetSymbolAddress((void**)&d_h1,   g_h1);
    float* d_qkv;  cudaGetSymbolAddress((void**)&d_qkv,  g_qkv);
    float* d_attn; cudaGetSymbolAddress((void**)&d_attn, g_attn);
    float* d_h2;   cudaGetSymbolAddress((void**)&d_h2,   g_h2);

    // 1. h = hidden + residual; res = h; g_h1 = rms(h)*ln1_w
    add_rms_kernel<<<kT, 256>>>(hidden, residual, ln1_w, res, d_h1);
    // 2. qkv = g_h1 @ w_qkv
    gemm_plain_kernel<<<dim3(kT/64, kQKV/64), 256>>>(d_h1, kH, w_qkv, kQKV, d_qkv, kQKV, kH, nullptr);
    // 3. QK rmsnorm + RoPE in place
    rope_kernel<<<dim3(kT, kNH + kNKV), 128>>>(positions, q_norm_w, k_norm_w);
    // 4-6. attention
    scores_kernel<<<dim3(kT/64, kT/64, kNH), 256>>>();
    softmax_kernel<<<dim3(kT, kNH), 256>>>();
    pv_kernel<<<dim3(kT/64, kHD/64, kNH), 256>>>();
    // 7. o-proj + residual add -> res (new residual, second output)
    gemm_plain_kernel<<<dim3(kT/64, kH/64), 256>>>(d_attn, kH, w_o, kH, res, kH, kH, res);
    // 8. g_h2 = rms(res)*ln2_w
    add_rms_kernel<<<kT, 256>>>(res, nullptr, ln2_w, nullptr, d_h2);
    // 9-12. routing
    moe_init_kernel<<<(kSlots + 255)/256, 256>>>();
    router_kernel<<<kT, 256>>>(gate_w);
    moe_setup_kernel<<<1, 1>>>();
    moe_scatter_kernel<<<(kT + 255)/256, 256>>>();
    // 13-15. expert MLPs (sparse, per-expert tiles)
    moe_gu_kernel<<<dim3(kTiles, 2*kI/64), 256>>>(w_gate_up);
    silu_kernel<<<(kSlots*kI)/256, 256>>>();
    moe_down_kernel<<<dim3(kTiles, kH/64), 256>>>(w_down);
    // 16. weighted combine -> out
    combine_kernel<<<kT, 256>>>(out);
}

// round 2
// speedup vs baseline: 2.0197x; 2.0197x over previous
#include <cuda_runtime.h>
#include <math.h>

// ---------------- problem constants ----------------
constexpr int kT   = 1024;
constexpr int kH   = 2048;
constexpr int kNH  = 16;
constexpr int kNKV = 4;
constexpr int kHD  = 128;
constexpr int kE   = 8;
constexpr int kI   = 768;
constexpr int kQKV = kNH*kHD + 2*kNKV*kHD;   // 3072
constexpr float kEPS = 1e-6f;
constexpr float kScale = 0.08838834764831845f; // 128^-0.5

constexpr int kSlots = 2560;   // 2*T + 8*64 padding headroom, multiple of 64
constexpr int kTiles = kSlots / 64; // 40

// ---------------- scratch (device globals; no allocation allowed) ----------------
__device__ float g_h1[kT*kH];
__device__ float g_qkv[kT*kQKV];
__device__ float g_scores[(size_t)kNH*kT*kT];
__device__ float g_attn[kT*kH];
__device__ float g_h2[kT*kH];
__device__ float g_gu[(size_t)kSlots*2*kI];
__device__ float g_act[(size_t)kSlots*kI];
__device__ float g_ds[(size_t)kSlots*kH];
__device__ int   g_tok[kSlots];
__device__ float g_wt[kSlots];
__device__ int   g_slot_of[kT*2];
__device__ int   g_topi[kT*2];
__device__ float g_topw[kT*2];
__device__ int   g_cnt[kE];
__device__ int   g_cursor[kE];
__device__ int   g_tile_e[kTiles];
__device__ int   g_ntiles;

// ---------------- tf32 helpers ----------------
__device__ __forceinline__ unsigned f2tf(float x) {
    unsigned r;
    asm("cvt.rna.tf32.f32 %0, %1;" : "=r"(r) : "f"(x));
    return r;
}
__device__ __forceinline__ void mma_tf32(float c[4],
                                         unsigned a0, unsigned a1, unsigned a2, unsigned a3,
                                         unsigned b0, unsigned b1) {
    asm volatile("mma.sync.aligned.m16n8k8.row.col.f32.tf32.tf32.f32 "
                 "{%0,%1,%2,%3}, {%4,%5,%6,%7}, {%8,%9}, {%0,%1,%2,%3};"
                 : "+f"(c[0]), "+f"(c[1]), "+f"(c[2]), "+f"(c[3])
                 : "r"(a0), "r"(a1), "r"(a2), "r"(a3), "r"(b0), "r"(b1));
}

// SMEM strides: A-side [m][36] -> frag addr (4g+t) conflict-free;
// B-side [k][72] -> frag addr (8t+g) conflict-free.
constexpr int kSA = 36;
constexpr int kSB = 72;

// Compute phase on one staged 64x32 (A) x 32x64 (B) chunk.
__device__ __forceinline__ void mma_compute(const unsigned* __restrict__ As,
                                            const unsigned* __restrict__ Bs,
                                            int wm, int wn, int g, int t,
                                            float acc[2][2][4]) {
    #pragma unroll
    for (int kk = 0; kk < 32; kk += 8) {
        unsigned a[2][4], b[2][2];
        #pragma unroll
        for (int im = 0; im < 2; im++) {
            int r = wm + im*16;
            a[im][0] = As[(r+g)*kSA   + kk + t];
            a[im][1] = As[(r+8+g)*kSA + kk + t];
            a[im][2] = As[(r+g)*kSA   + kk + t + 4];
            a[im][3] = As[(r+8+g)*kSA + kk + t + 4];
        }
        #pragma unroll
        for (int jn = 0; jn < 2; jn++) {
            int c = wn + jn*8 + g;
            b[jn][0] = Bs[(kk+t)*kSB   + c];
            b[jn][1] = Bs[(kk+t+4)*kSB + c];
        }
        #pragma unroll
        for (int im = 0; im < 2; im++)
            #pragma unroll
            for (int jn = 0; jn < 2; jn++)
                mma_tf32(acc[im][jn], a[im][0], a[im][1], a[im][2], a[im][3],
                         b[jn][0], b[jn][1]);
    }
}

// B-transposed compute: Bst is [n][kSA] (64 rows of 32 k)
__device__ __forceinline__ void mma_compute_tt(const unsigned* __restrict__ As,
                                               const unsigned* __restrict__ Bst,
                                               int wm, int wn, int g, int t,
                                               float acc[2][2][4]) {
    #pragma unroll
    for (int kk = 0; kk < 32; kk += 8) {
        unsigned a[2][4], b[2][2];
        #pragma unroll
        for (int im = 0; im < 2; im++) {
            int r = wm + im*16;
            a[im][0] = As[(r+g)*kSA   + kk + t];
            a[im][1] = As[(r+8+g)*kSA + kk + t];
            a[im][2] = As[(r+g)*kSA   + kk + t + 4];
            a[im][3] = As[(r+8+g)*kSA + kk + t + 4];
        }
        #pragma unroll
        for (int jn = 0; jn < 2; jn++) {
            int c = wn + jn*8 + g;
            b[jn][0] = Bst[c*kSA + kk + t];
            b[jn][1] = Bst[c*kSA + kk + t + 4];
        }
        #pragma unroll
        for (int im = 0; im < 2; im++)
            #pragma unroll
            for (int jn = 0; jn < 2; jn++)
                mma_tf32(acc[im][jn], a[im][0], a[im][1], a[im][2], a[im][3],
                         b[jn][0], b[jn][1]);
    }
}

// Stage a 64x32 fp32 chunk (row-major, ld) into [64][kSA] tf32 SMEM.
__device__ __forceinline__ void stage_A(const float* __restrict__ A, int lda, int kk0,
                                        unsigned* __restrict__ As) {
    const int tid = threadIdx.x;
    #pragma unroll
    for (int q = 0; q < 2; q++) {
        int e = tid + q*256;          // 0..511
        int m = e >> 3, k4 = e & 7;
        float4 v = *reinterpret_cast<const float4*>(A + (size_t)m*lda + kk0 + k4*4);
        uint4 u = make_uint4(f2tf(v.x), f2tf(v.y), f2tf(v.z), f2tf(v.w));
        *reinterpret_cast<uint4*>(&As[m*kSA + k4*4]) = u;
    }
}
// Stage gathered rows (-1 => zeros)
__device__ __forceinline__ void stage_A_gather(const float* __restrict__ Abase, int lda,
                                               const int* __restrict__ rows, int kk0,
                                               unsigned* __restrict__ As) {
    const int tid = threadIdx.x;
    #pragma unroll
    for (int q = 0; q < 2; q++) {
        int e = tid + q*256;
        int m = e >> 3, k4 = e & 7;
        int rt = rows[m];
        uint4 u;
        if (rt >= 0) {
            float4 v = *reinterpret_cast<const float4*>(Abase + (size_t)rt*lda + kk0 + k4*4);
            u = make_uint4(f2tf(v.x), f2tf(v.y), f2tf(v.z), f2tf(v.w));
        } else {
            u = make_uint4(0u, 0u, 0u, 0u);
        }
        *reinterpret_cast<uint4*>(&As[m*kSA + k4*4]) = u;
    }
}
// Stage 32x64 B chunk (row-major K x N, ldb) into [32][kSB]
__device__ __forceinline__ void stage_B(const float* __restrict__ B, int ldb, int kk0,
                                        unsigned* __restrict__ Bs) {
    const int tid = threadIdx.x;
    #pragma unroll
    for (int q = 0; q < 2; q++) {
        int e = tid + q*256;
        int k = e >> 4, n4 = e & 15;
        float4 v = *reinterpret_cast<const float4*>(B + (size_t)(kk0+k)*ldb + n4*4);
        uint4 u = make_uint4(f2tf(v.x), f2tf(v.y), f2tf(v.z), f2tf(v.w));
        *reinterpret_cast<uint4*>(&Bs[k*kSB + n4*4]) = u;
    }
}

// ---------------- fused add + RMSNorm ----------------
__global__ void add_rms_kernel(const float* __restrict__ x, const float* __restrict__ r,
                               const float* __restrict__ w, float* __restrict__ res_out,
                               float* __restrict__ h_out) {
    const int t = blockIdx.x, tid = threadIdx.x;
    const float* xp = x + (size_t)t*kH;
    const float* rp = r ? r + (size_t)t*kH : nullptr;
    float v[8]; float ss = 0.f;
    #pragma unroll
    for (int i = 0; i < 8; i++) {
        int idx = tid + i*256;
        float val = xp[idx];
        if (rp) val += rp[idx];
        v[i] = val; ss += val*val;
    }
    __shared__ float sh[256];
    sh[tid] = ss; __syncthreads();
    for (int s = 128; s > 0; s >>= 1) { if (tid < s) sh[tid] += sh[tid+s]; __syncthreads(); }
    float scale = rsqrtf(sh[0]/(float)kH + kEPS);
    #pragma unroll
    for (int i = 0; i < 8; i++) {
        int idx = tid + i*256;
        if (res_out) res_out[(size_t)t*kH + idx] = v[i];
        h_out[(size_t)t*kH + idx] = v[i]*scale*w[idx];
    }
}

// ---------------- generic GEMM (optional fused residual add) ----------------
__global__ void gemm_plain_kernel(const float* __restrict__ A, int lda,
                                  const float* __restrict__ B, int ldb,
                                  float* __restrict__ C, int ldc, int Kdim,
                                  const float* __restrict__ addsrc) {
    const int row0 = blockIdx.x*64, col0 = blockIdx.y*64;
    __shared__ __align__(16) unsigned As[64*kSA];
    __shared__ __align__(16) unsigned Bs[32*kSB];
    const int lane = threadIdx.x & 31, warp = threadIdx.x >> 5;
    const int wm = (warp & 1)*32, wn = (warp >> 1)*16;
    const int g = lane >> 2, t = lane & 3;
    float acc[2][2][4] = {};
    const float* Ab = A + (size_t)row0*lda;
    const float* Bb = B + col0;
    for (int kk0 = 0; kk0 < Kdim; kk0 += 32) {
        stage_A(Ab, lda, kk0, As);
        stage_B(Bb, ldb, kk0, Bs);
        __syncthreads();
        mma_compute(As, Bs, wm, wn, g, t, acc);
        __syncthreads();
    }
    #pragma unroll
    for (int im = 0; im < 2; im++)
        #pragma unroll
        for (int jn = 0; jn < 2; jn++) {
            int r0 = row0 + wm + im*16 + g;
            int c0 = col0 + wn + jn*8 + 2*t;
            #pragma unroll
            for (int hh = 0; hh < 2; hh++) {
                int rr = r0 + hh*8;
                float v0 = acc[im][jn][hh*2+0], v1 = acc[im][jn][hh*2+1];
                if (addsrc) {
                    v0 += addsrc[(size_t)rr*ldc + c0];
                    v1 += addsrc[(size_t)rr*ldc + c0 + 1];
                }
                C[(size_t)rr*ldc + c0]     = v0;
                C[(size_t)rr*ldc + c0 + 1] = v1;
            }
        }
}

// ---------------- QK-RMSNorm + RoPE (in place on g_qkv) ----------------
__global__ void rope_kernel(const int* __restrict__ positions,
                            const float* __restrict__ q_norm_w,
                            const float* __restrict__ k_norm_w) {
    const int t = blockIdx.x, hh = blockIdx.y, lane = threadIdx.x; // 128 threads
    float* ptr = g_qkv + (size_t)t*kQKV + (hh < kNH ? hh*kHD : kNH*kHD + (hh-kNH)*kHD);
    const float* nw = (hh < kNH) ? q_norm_w : k_norm_w;
    float v = ptr[lane];
    __shared__ float sred[128];
    sred[lane] = v*v; __syncthreads();
    for (int s = 64; s > 0; s >>= 1) { if (lane < s) sred[lane] += sred[lane+s]; __syncthreads(); }
    float scale = rsqrtf(sred[0]/(float)kHD + kEPS);
    float xn = v*scale*nw[lane];
    __shared__ float sh[128];
    sh[lane] = xn; __syncthreads();
    int j = lane & 63;
    double inv = exp(-(double)j/64.0 * log(1.0e6));
    double ang = (double)positions[t] * inv;
    float c = (float)cos(ang), s = (float)sin(ang);
    float outv;
    if (lane < 64) outv = sh[lane]*c - sh[lane+64]*s;
    else           outv = sh[lane]*c + sh[lane-64]*s;
    ptr[lane] = outv;
}

// ---------------- attention scores ----------------
__global__ void scores_kernel() {
    const int qt = blockIdx.x, kt = blockIdx.y, h = blockIdx.z;
    if (kt > qt) return;
    const float* Q  = g_qkv + (size_t)qt*64*kQKV + h*kHD;
    const float* Kp = g_qkv + (size_t)kt*64*kQKV + kNH*kHD + (h >> 2)*kHD;
    __shared__ __align__(16) unsigned As[64*kSA];
    __shared__ __align__(16) unsigned Bst[64*kSA];
    const int lane = threadIdx.x & 31, warp = threadIdx.x >> 5;
    const int wm = (warp & 1)*32, wn = (warp >> 1)*16;
    const int g = lane >> 2, t = lane & 3;
    float acc[2][2][4] = {};
    for (int kk0 = 0; kk0 < kHD; kk0 += 32) {
        stage_A(Q,  kQKV, kk0, As);
        stage_A(Kp, kQKV, kk0, Bst);
        __syncthreads();
        mma_compute_tt(As, Bst, wm, wn, g, t, acc);
        __syncthreads();
    }
    const int row0 = qt*64, col0 = kt*64;
    #pragma unroll
    for (int im = 0; im < 2; im++)
        #pragma unroll
        for (int jn = 0; jn < 2; jn++) {
            int r0 = row0 + wm + im*16 + g;
            int c0 = col0 + wn + jn*8 + 2*t;
            #pragma unroll
            for (int hh = 0; hh < 2; hh++) {
                int qi = r0 + hh*8;
                float v0 = acc[im][jn][hh*2+0]*kScale;
                float v1 = acc[im][jn][hh*2+1]*kScale;
                if (c0   > qi) v0 = -1e9f;
                if (c0+1 > qi) v1 = -1e9f;
                g_scores[((size_t)h*kT + qi)*kT + c0]     = v0;
                g_scores[((size_t)h*kT + qi)*kT + c0 + 1] = v1;
            }
        }
}

// ---------------- row softmax (causal; zero-fill only to tile boundary) ----------------
__global__ void softmax_kernel() {
    const int q = blockIdx.x, h = blockIdx.y, tid = threadIdx.x;
    float* row = g_scores + ((size_t)h*kT + q)*kT;
    const int tend = ((q >> 6) + 1) << 6;   // 64-tile boundary past q
    __shared__ float sh[256];
    float lmax = -3.4e38f;
    for (int k = tid; k <= q; k += 256) lmax = fmaxf(lmax, row[k]);
    sh[tid] = lmax; __syncthreads();
    for (int s = 128; s > 0; s >>= 1) { if (tid < s) sh[tid] = fmaxf(sh[tid], sh[tid+s]); __syncthreads(); }
    float m = sh[0]; __syncthreads();
    float lsum = 0.f;
    for (int k = tid; k <= q; k += 256) { float e = __expf(row[k]-m); row[k] = e; lsum += e; }
    sh[tid] = lsum; __syncthreads();
    for (int s = 128; s > 0; s >>= 1) { if (tid < s) sh[tid] += sh[tid+s]; __syncthreads(); }
    float inv = 1.f/sh[0];
    for (int k = tid; k < tend; k += 256) row[k] = (k <= q) ? row[k]*inv : 0.f;
}

// ---------------- PV: O_h = P V_h  (causal-trimmed K) ----------------
__global__ void pv_kernel() {
    const int qt = blockIdx.x, nt = blockIdx.y, h = blockIdx.z;
    const int row0 = qt*64, col0 = nt*64;
    const int Kdim = (qt + 1)*64;
    const float* A = g_scores + ((size_t)h*kT + row0)*kT;
    const float* B = g_qkv + kNH*kHD + kNKV*kHD + (h >> 2)*kHD + col0;
    __shared__ __align__(16) unsigned As[64*kSA];
    __shared__ __align__(16) unsigned Bs[32*kSB];
    const int lane = threadIdx.x & 31, warp = threadIdx.x >> 5;
    const int wm = (warp & 1)*32, wn = (warp >> 1)*16;
    const int g = lane >> 2, t = lane & 3;
    float acc[2][2][4] = {};
    for (int kk0 = 0; kk0 < Kdim; kk0 += 32) {
        stage_A(A, kT, kk0, As);
        stage_B(B, kQKV, kk0, Bs);
        __syncthreads();
        mma_compute(As, Bs, wm, wn, g, t, acc);
        __syncthreads();
    }
    #pragma unroll
    for (int im = 0; im < 2; im++)
        #pragma unroll
        for (int jn = 0; jn < 2; jn++) {
            int r0 = row0 + wm + im*16 + g;
            int c0 = col0 + wn + jn*8 + 2*t;
            #pragma unroll
            for (int hh = 0; hh < 2; hh++) {
                int rr = r0 + hh*8;
                g_attn[(size_t)rr*kH + h*kHD + c0]     = acc[im][jn][hh*2+0];
                g_attn[(size_t)rr*kH + h*kHD + c0 + 1] = acc[im][jn][hh*2+1];
            }
        }
}

// ---------------- router ----------------
__global__ void router_kernel(const float* __restrict__ gate_w) {
    const int t = blockIdx.x, tid = threadIdx.x;
    const float* hp = g_h2 + (size_t)t*kH;
    float acc[kE] = {};
    for (int k = tid; k < kH; k += 256) {
        float hv = hp[k];
        const float* gw = gate_w + (size_t)k*kE;
        #pragma unroll
        for (int e = 0; e < kE; e++) acc[e] += hv*gw[e];
    }
    __shared__ float sh[kE][256];
    #pragma unroll
    for (int e = 0; e < kE; e++) sh[e][tid] = acc[e];
    __syncthreads();
    for (int s = 128; s > 0; s >>= 1) {
        if (tid < s) {
            #pragma unroll
            for (int e = 0; e < kE; e++) sh[e][tid] += sh[e][tid+s];
        }
        __syncthreads();
    }
    if (tid == 0) {
        float l[kE], mx = -3.4e38f;
        #pragma unroll
        for (int e = 0; e < kE; e++) { l[e] = sh[e][0]; mx = fmaxf(mx, l[e]); }
        float sum = 0.f;
        #pragma unroll
        for (int e = 0; e < kE; e++) { l[e] = __expf(l[e]-mx); sum += l[e]; }
        float isum = 1.f/sum;
        float best = -1.f, second = -1.f; int bi = 0, si = 0;
        #pragma unroll
        for (int e = 0; e < kE; e++) {
            float p = l[e]*isum;
            if (p > best) { second = best; si = bi; best = p; bi = e; }
            else if (p > second) { second = p; si = e; }
        }
        float denom = 1.f/(best + second);
        g_topi[t*2]   = bi; g_topw[t*2]   = best*denom;
        g_topi[t*2+1] = si; g_topw[t*2+1] = second*denom;
        atomicAdd(&g_cnt[bi], 1);
        atomicAdd(&g_cnt[si], 1);
    }
}

__global__ void moe_init_kernel() {
    int i = blockIdx.x*256 + threadIdx.x;
    if (i < kE) { g_cnt[i] = 0; }
    if (i < kSlots) g_tok[i] = -1;
}

__global__ void moe_setup_kernel() {
    int off = 0, tile = 0;
    for (int e = 0; e < kE; e++) {
        g_cursor[e] = off;
        int seg = ((g_cnt[e] + 63)/64)*64;
        for (int i = 0; i < seg/64; i++) g_tile_e[tile++] = e;
        off += seg;
    }
    g_ntiles = tile;
}

__global__ void moe_scatter_kernel() {
    int t = blockIdx.x*256 + threadIdx.x;
    if (t >= kT) return;
    #pragma unroll
    for (int k = 0; k < 2; k++) {
        int e = g_topi[t*2+k];
        int pos = atomicAdd(&g_cursor[e], 1);
        g_tok[pos] = t;
        g_wt[pos]  = g_topw[t*2+k];
        g_slot_of[t*2+k] = pos;
    }
}

// ---------------- MoE GEMM 1: gate_up (gathered rows) ----------------
__global__ void moe_gu_kernel(const float* __restrict__ w_gate_up) {
    const int tile = blockIdx.x;
    if (tile >= g_ntiles) return;
    const int e = g_tile_e[tile];
    const int col0 = blockIdx.y*64;
    const float* B = w_gate_up + (size_t)e*kH*2*kI + col0;
    __shared__ __align__(16) unsigned As[64*kSA];
    __shared__ __align__(16) unsigned Bs[32*kSB];
    __shared__ int rows[64];
    const int tid = threadIdx.x;
    if (tid < 64) rows[tid] = g_tok[tile*64 + tid];
    __syncthreads();
    const int lane = tid & 31, warp = tid >> 5;
    const int wm = (warp & 1)*32, wn = (warp >> 1)*16;
    const int g = lane >> 2, t = lane & 3;
    float acc[2][2][4] = {};
    for (int kk0 = 0; kk0 < kH; kk0 += 32) {
        stage_A_gather(g_h2, kH, rows, kk0, As);
        stage_B(B, 2*kI, kk0, Bs);
        __syncthreads();
        mma_compute(As, Bs, wm, wn, g, t, acc);
        __syncthreads();
    }
    #pragma unroll
    for (int im = 0; im < 2; im++)
        #pragma unroll
        for (int jn = 0; jn < 2; jn++) {
            int r0 = wm + im*16 + g;
            int c0 = col0 + wn + jn*8 + 2*t;
            #pragma unroll
            for (int hh = 0; hh < 2; hh++) {
                int slot = tile*64 + r0 + hh*8;
                g_gu[(size_t)slot*2*kI + c0]     = acc[im][jn][hh*2+0];
                g_gu[(size_t)slot*2*kI + c0 + 1] = acc[im][jn][hh*2+1];
            }
        }
}

__global__ void silu_kernel() {
    int idx = blockIdx.x*256 + threadIdx.x;
    int slot = idx / kI, j = idx % kI;
    if (slot >= g_ntiles*64) return;
    float g = g_gu[(size_t)slot*2*kI + j];
    float u = g_gu[(size_t)slot*2*kI + kI + j];
    g_act[idx] = (g / (1.f + __expf(-g))) * u;
}

// ---------------- MoE GEMM 2: down ----------------
__global__ void moe_down_kernel(const float* __restrict__ w_down) {
    const int tile = blockIdx.x;
    if (tile >= g_ntiles) return;
    const int e = g_tile_e[tile];
    const int col0 = blockIdx.y*64;
    const float* A = g_act + (size_t)tile*64*kI;
    const float* B = w_down + (size_t)e*kI*kH + col0;
    __shared__ __align__(16) unsigned As[64*kSA];
    __shared__ __align__(16) unsigned Bs[32*kSB];
    const int lane = threadIdx.x & 31, warp = threadIdx.x >> 5;
    const int wm = (warp & 1)*32, wn = (warp >> 1)*16;
    const int g = lane >> 2, t = lane & 3;
    float acc[2][2][4] = {};
    for (int kk0 = 0; kk0 < kI; kk0 += 32) {
        stage_A(A, kI, kk0, As);
        stage_B(B, kH, kk0, Bs);
        __syncthreads();
        mma_compute(As, Bs, wm, wn, g, t, acc);
        __syncthreads();
    }
    #pragma unroll
    for (int im = 0; im < 2; im++)
        #pragma unroll
        for (int jn = 0; jn < 2; jn++) {
            int r0 = wm + im*16 + g;
            int c0 = col0 + wn + jn*8 + 2*t;
            #pragma unroll
            for (int hh = 0; hh < 2; hh++) {
                int slot = tile*64 + r0 + hh*8;
                g_ds[(size_t)slot*kH + c0]     = acc[im][jn][hh*2+0];
                g_ds[(size_t)slot*kH + c0 + 1] = acc[im][jn][hh*2+1];
            }
        }
}

__global__ void combine_kernel(float* __restrict__ out) {
    const int t = blockIdx.x;
    const int s0 = g_slot_of[t*2], s1 = g_slot_of[t*2+1];
    const float w0 = g_wt[s0], w1 = g_wt[s1];
    for (int j = threadIdx.x; j < kH; j += 256)
        out[(size_t)t*kH + j] = w0*g_ds[(size_t)s0*kH + j] + w1*g_ds[(size_t)s1*kH + j];
}

// ---------------- launcher ----------------
extern "C" void kernel_launch(void* const* d_in, const int* in_sizes, int n_in,
                              void* d_out, int out_size) {
    const int*   positions = (const int*)  d_in[0];
    const float* hidden    = (const float*)d_in[1];
    const float* residual  = (const float*)d_in[2];
    const float* w_qkv     = (const float*)d_in[3];
    const float* w_o       = (const float*)d_in[4];
    const float* q_norm_w  = (const float*)d_in[5];
    const float* k_norm_w  = (const float*)d_in[6];
    const float* ln1_w     = (const float*)d_in[7];
    const float* ln2_w     = (const float*)d_in[8];
    const float* gate_w    = (const float*)d_in[9];
    const float* w_gate_up = (const float*)d_in[10];
    const float* w_down    = (const float*)d_in[11];
    float* out = (float*)d_out;
    float* res = out + (size_t)kT*kH;

    float* d_h1;   cudaGetSymbolAddress((void**)&d_h1,   g_h1);
    float* d_qkv;  cudaGetSymbolAddress((void**)&d_qkv,  g_qkv);
    float* d_attn; cudaGetSymbolAddress((void**)&d_attn, g_attn);
    float* d_h2;   cudaGetSymbolAddress((void**)&d_h2,   g_h2);

    add_rms_kernel<<<kT, 256>>>(hidden, residual, ln1_w, res, d_h1);
    gemm_plain_kernel<<<dim3(kT/64, kQKV/64), 256>>>(d_h1, kH, w_qkv, kQKV, d_qkv, kQKV, kH, nullptr);
    rope_kernel<<<dim3(kT, kNH + kNKV), 128>>>(positions, q_norm_w, k_norm_w);
    scores_kernel<<<dim3(kT/64, kT/64, kNH), 256>>>();
    softmax_kernel<<<dim3(kT, kNH), 256>>>();
    pv_kernel<<<dim3(kT/64, kHD/64, kNH), 256>>>();
    gemm_plain_kernel<<<dim3(kT/64, kH/64), 256>>>(d_attn, kH, w_o, kH, res, kH, kH, res);
    add_rms_kernel<<<kT, 256>>>(res, nullptr, ln2_w, nullptr, d_h2);
    moe_init_kernel<<<(kSlots + 255)/256, 256>>>();
    router_kernel<<<kT, 256>>>(gate_w);
    moe_setup_kernel<<<1, 1>>>();
    moe_scatter_kernel<<<(kT + 255)/256, 256>>>();
    moe_gu_kernel<<<dim3(kTiles, 2*kI/64), 256>>>(w_gate_up);
    silu_kernel<<<(kSlots*kI)/256, 256>>>();
    moe_down_kernel<<<dim3(kTiles, kH/64), 256>>>(w_down);
    combine_kernel<<<kT, 256>>>(out);
}

// round 3
// speedup vs baseline: 2.2245x; 1.1014x over previous
#include <cuda_runtime.h>
#include <math.h>

// ---------------- problem constants ----------------
constexpr int kT   = 1024;
constexpr int kH   = 2048;
constexpr int kNH  = 16;
constexpr int kNKV = 4;
constexpr int kHD  = 128;
constexpr int kE   = 8;
constexpr int kI   = 768;
constexpr int kQKV = kNH*kHD + 2*kNKV*kHD;   // 3072
constexpr float kEPS = 1e-6f;
constexpr float kScale = 0.08838834764831845f; // 128^-0.5

constexpr int kSlots = 3072;   // 2*T + 8*128 padding headroom, multiple of 128
constexpr int kTiles = kSlots / 128; // 24

// ---------------- scratch ----------------
__device__ float g_h1[kT*kH];
__device__ float g_qkv[kT*kQKV];
__device__ float g_scores[(size_t)kNH*kT*kT];
__device__ float g_attn[kT*kH];
__device__ float g_h2[kT*kH];
__device__ float g_gu[(size_t)kSlots*2*kI];
__device__ float g_act[(size_t)kSlots*kI];
__device__ float g_ds[(size_t)kSlots*kH];
__device__ int   g_tok[kSlots];
__device__ float g_wt[kSlots];
__device__ int   g_slot_of[kT*2];
__device__ int   g_topi[kT*2];
__device__ float g_topw[kT*2];
__device__ int   g_cnt[kE];
__device__ int   g_cursor[kE];
__device__ int   g_tile_e[kTiles];
__device__ int   g_ntiles;

// ---------------- tf32 helpers ----------------
__device__ __forceinline__ unsigned f2tf(float x) {
    unsigned r;
    asm("cvt.rna.tf32.f32 %0, %1;" : "=r"(r) : "f"(x));
    return r;
}
__device__ __forceinline__ void mma_tf32(float c[4],
                                         unsigned a0, unsigned a1, unsigned a2, unsigned a3,
                                         unsigned b0, unsigned b1) {
    asm volatile("mma.sync.aligned.m16n8k8.row.col.f32.tf32.tf32.f32 "
                 "{%0,%1,%2,%3}, {%4,%5,%6,%7}, {%8,%9}, {%0,%1,%2,%3};"
                 : "+f"(c[0]), "+f"(c[1]), "+f"(c[2]), "+f"(c[3])
                 : "r"(a0), "r"(a1), "r"(a2), "r"(a3), "r"(b0), "r"(b1));
}

constexpr int kSA = 36;   // A-side SMEM row stride (words), conflict-free 4g+t
constexpr int kSB = 136;  // B-side SMEM row stride (words), conflict-free 8t+g
constexpr int kAOff = 128*kSA;  // one A buffer (words)
constexpr int kBOff = 32*kSB;   // one B buffer (words)

// ---------- global->register prefetch ----------
__device__ __forceinline__ void ldA128(const float* __restrict__ A, int lda, int kk0, float4 v[4]) {
    const int tid = threadIdx.x;
    #pragma unroll
    for (int q = 0; q < 4; q++) {
        int e = tid + q*256;              // 0..1023
        int m = e >> 3, k4 = e & 7;
        v[q] = *reinterpret_cast<const float4*>(A + (size_t)m*lda + kk0 + k4*4);
    }
}
__device__ __forceinline__ void ldA128_gather(const float* __restrict__ Ab, int lda,
                                              const int* __restrict__ rows, int kk0, float4 v[4]) {
    const int tid = threadIdx.x;
    #pragma unroll
    for (int q = 0; q < 4; q++) {
        int e = tid + q*256;
        int m = e >> 3, k4 = e & 7;
        int rt = rows[m];
        v[q] = (rt >= 0) ? *reinterpret_cast<const float4*>(Ab + (size_t)rt*lda + kk0 + k4*4)
                         : make_float4(0.f, 0.f, 0.f, 0.f);
    }
}
__device__ __forceinline__ void ldB128(const float* __restrict__ B, int ldb, int kk0, float4 v[4]) {
    const int tid = threadIdx.x;
    #pragma unroll
    for (int q = 0; q < 4; q++) {
        int e = tid + q*256;
        int k = e >> 5, n4 = e & 31;
        v[q] = *reinterpret_cast<const float4*>(B + (size_t)(kk0+k)*ldb + n4*4);
    }
}
// ---------- register->smem stores (tf32 convert) ----------
__device__ __forceinline__ void stA128(unsigned* __restrict__ As, const float4 v[4]) {
    const int tid = threadIdx.x;
    #pragma unroll
    for (int q = 0; q < 4; q++) {
        int e = tid + q*256;
        int m = e >> 3, k4 = e & 7;
        *reinterpret_cast<uint4*>(&As[m*kSA + k4*4]) =
            make_uint4(f2tf(v[q].x), f2tf(v[q].y), f2tf(v[q].z), f2tf(v[q].w));
    }
}
__device__ __forceinline__ void stB128(unsigned* __restrict__ Bs, const float4 v[4]) {
    const int tid = threadIdx.x;
    #pragma unroll
    for (int q = 0; q < 4; q++) {
        int e = tid + q*256;
        int k = e >> 5, n4 = e & 31;
        *reinterpret_cast<uint4*>(&Bs[k*kSB + n4*4]) =
            make_uint4(f2tf(v[q].x), f2tf(v[q].y), f2tf(v[q].z), f2tf(v[q].w));
    }
}

// ---------- compute on one staged chunk: A[128][32] x B[32][128] ----------
__device__ __forceinline__ void compute128(const unsigned* __restrict__ As,
                                           const unsigned* __restrict__ Bs,
                                           int wm, int wn, int g, int t,
                                           float acc[4][4][4]) {
    #pragma unroll
    for (int kk = 0; kk < 32; kk += 8) {
        unsigned a[4][4], b[4][2];
        #pragma unroll
        for (int im = 0; im < 4; im++) {
            int r = wm + im*16;
            a[im][0] = As[(r+g)*kSA   + kk + t];
            a[im][1] = As[(r+8+g)*kSA + kk + t];
            a[im][2] = As[(r+g)*kSA   + kk + t + 4];
            a[im][3] = As[(r+8+g)*kSA + kk + t + 4];
        }
        #pragma unroll
        for (int jn = 0; jn < 4; jn++) {
            int c = wn + jn*8 + g;
            b[jn][0] = Bs[(kk+t)*kSB   + c];
            b[jn][1] = Bs[(kk+t+4)*kSB + c];
        }
        #pragma unroll
        for (int im = 0; im < 4; im++)
            #pragma unroll
            for (int jn = 0; jn < 4; jn++)
                mma_tf32(acc[im][jn], a[im][0], a[im][1], a[im][2], a[im][3],
                         b[jn][0], b[jn][1]);
    }
}
// B-transposed: Bst is [128 n-rows][kSA] of 32 k
__device__ __forceinline__ void compute128_tt(const unsigned* __restrict__ As,
                                              const unsigned* __restrict__ Bst,
                                              int wm, int wn, int g, int t,
                                              float acc[4][4][4]) {
    #pragma unroll
    for (int kk = 0; kk < 32; kk += 8) {
        unsigned a[4][4], b[4][2];
        #pragma unroll
        for (int im = 0; im < 4; im++) {
            int r = wm + im*16;
            a[im][0] = As[(r+g)*kSA   + kk + t];
            a[im][1] = As[(r+8+g)*kSA + kk + t];
            a[im][2] = As[(r+g)*kSA   + kk + t + 4];
            a[im][3] = As[(r+8+g)*kSA + kk + t + 4];
        }
        #pragma unroll
        for (int jn = 0; jn < 4; jn++) {
            int c = wn + jn*8 + g;
            b[jn][0] = Bst[c*kSA + kk + t];
            b[jn][1] = Bst[c*kSA + kk + t + 4];
        }
        #pragma unroll
        for (int im = 0; im < 4; im++)
            #pragma unroll
            for (int jn = 0; jn < 4; jn++)
                mma_tf32(acc[im][jn], a[im][0], a[im][1], a[im][2], a[im][3],
                         b[jn][0], b[jn][1]);
    }
}

constexpr size_t kPlainSmem = (size_t)(2*kAOff + 2*kBOff)*4;  // 71680 B
constexpr size_t kTTSmem    = (size_t)(4*kAOff)*4;            // 73728 B

// ---------------- fused add + RMSNorm ----------------
__global__ void add_rms_kernel(const float* __restrict__ x, const float* __restrict__ r,
                               const float* __restrict__ w, float* __restrict__ res_out,
                               float* __restrict__ h_out) {
    const int t = blockIdx.x, tid = threadIdx.x;
    const float* xp = x + (size_t)t*kH;
    const float* rp = r ? r + (size_t)t*kH : nullptr;
    float v[8]; float ss = 0.f;
    #pragma unroll
    for (int i = 0; i < 8; i++) {
        int idx = tid + i*256;
        float val = xp[idx];
        if (rp) val += rp[idx];
        v[i] = val; ss += val*val;
    }
    __shared__ float sh[256];
    sh[tid] = ss; __syncthreads();
    for (int s = 128; s > 0; s >>= 1) { if (tid < s) sh[tid] += sh[tid+s]; __syncthreads(); }
    float scale = rsqrtf(sh[0]/(float)kH + kEPS);
    #pragma unroll
    for (int i = 0; i < 8; i++) {
        int idx = tid + i*256;
        if (res_out) res_out[(size_t)t*kH + idx] = v[i];
        h_out[(size_t)t*kH + idx] = v[i]*scale*w[idx];
    }
}

// ---------------- generic 128x128 GEMM (optional fused residual add) ----------------
__global__ void __launch_bounds__(256)
gemm_plain_kernel(const float* __restrict__ A, int lda,
                  const float* __restrict__ B, int ldb,
                  float* __restrict__ C, int ldc, int Kdim,
                  const float* __restrict__ addsrc) {
    extern __shared__ unsigned smem[];
    unsigned* As = smem;                // [2][kAOff]
    unsigned* Bs = smem + 2*kAOff;      // [2][kBOff]
    const int row0 = blockIdx.x*128, col0 = blockIdx.y*128;
    const int lane = threadIdx.x & 31, warp = threadIdx.x >> 5;
    const int wm = (warp & 1)*64, wn = (warp >> 1)*32;
    const int g = lane >> 2, t = lane & 3;
    const float* Ab = A + (size_t)row0*lda;
    const float* Bb = B + col0;
    float acc[4][4][4] = {};
    float4 va[4], vb[4];
    ldA128(Ab, lda, 0, va); ldB128(Bb, ldb, 0, vb);
    stA128(As, va); stB128(Bs, vb);
    __syncthreads();
    const int nk = Kdim >> 5;
    for (int i = 0; i < nk; i++) {
        int p = i & 1;
        if (i+1 < nk) { ldA128(Ab, lda, (i+1)*32, va); ldB128(Bb, ldb, (i+1)*32, vb); }
        compute128(As + p*kAOff, Bs + p*kBOff, wm, wn, g, t, acc);
        if (i+1 < nk) { stA128(As + (1-p)*kAOff, va); stB128(Bs + (1-p)*kBOff, vb); }
        __syncthreads();
    }
    #pragma unroll
    for (int im = 0; im < 4; im++)
        #pragma unroll
        for (int jn = 0; jn < 4; jn++) {
            int r0 = row0 + wm + im*16 + g;
            int c0 = col0 + wn + jn*8 + 2*t;
            #pragma unroll
            for (int hh = 0; hh < 2; hh++) {
                int rr = r0 + hh*8;
                float v0 = acc[im][jn][hh*2+0], v1 = acc[im][jn][hh*2+1];
                if (addsrc) {
                    v0 += addsrc[(size_t)rr*ldc + c0];
                    v1 += addsrc[(size_t)rr*ldc + c0 + 1];
                }
                C[(size_t)rr*ldc + c0]     = v0;
                C[(size_t)rr*ldc + c0 + 1] = v1;
            }
        }
}

// ---------------- QK-RMSNorm + RoPE ----------------
__global__ void rope_kernel(const int* __restrict__ positions,
                            const float* __restrict__ q_norm_w,
                            const float* __restrict__ k_norm_w) {
    const int t = blockIdx.x, hh = blockIdx.y, lane = threadIdx.x; // 128 threads
    float* ptr = g_qkv + (size_t)t*kQKV + (hh < kNH ? hh*kHD : kNH*kHD + (hh-kNH)*kHD);
    const float* nw = (hh < kNH) ? q_norm_w : k_norm_w;
    float v = ptr[lane];
    __shared__ float sred[128];
    sred[lane] = v*v; __syncthreads();
    for (int s = 64; s > 0; s >>= 1) { if (lane < s) sred[lane] += sred[lane+s]; __syncthreads(); }
    float scale = rsqrtf(sred[0]/(float)kHD + kEPS);
    float xn = v*scale*nw[lane];
    __shared__ float sh[128];
    sh[lane] = xn; __syncthreads();
    int j = lane & 63;
    double inv = exp(-(double)j/64.0 * log(1.0e6));
    double ang = (double)positions[t] * inv;
    float c = (float)cos(ang), s = (float)sin(ang);
    float outv;
    if (lane < 64) outv = sh[lane]*c - sh[lane+64]*s;
    else           outv = sh[lane]*c + sh[lane-64]*s;
    ptr[lane] = outv;
}

// ---------------- attention scores (128x128 tiles) ----------------
__global__ void __launch_bounds__(256) scores_kernel() {
    const int qt = blockIdx.x, kt = blockIdx.y, h = blockIdx.z;
    if (kt > qt) return;
    extern __shared__ unsigned smem[];
    unsigned* As  = smem;              // [2][kAOff]
    unsigned* Bst = smem + 2*kAOff;    // [2][kAOff]
    const float* Q  = g_qkv + (size_t)qt*128*kQKV + h*kHD;
    const float* Kp = g_qkv + (size_t)kt*128*kQKV + kNH*kHD + (h >> 2)*kHD;
    const int lane = threadIdx.x & 31, warp = threadIdx.x >> 5;
    const int wm = (warp & 1)*64, wn = (warp >> 1)*32;
    const int g = lane >> 2, t = lane & 3;
    float acc[4][4][4] = {};
    float4 va[4], vb[4];
    ldA128(Q, kQKV, 0, va); ldA128(Kp, kQKV, 0, vb);
    stA128(As, va); stA128(Bst, vb);
    __syncthreads();
    const int nk = kHD >> 5;   // 4
    for (int i = 0; i < nk; i++) {
        int p = i & 1;
        if (i+1 < nk) { ldA128(Q, kQKV, (i+1)*32, va); ldA128(Kp, kQKV, (i+1)*32, vb); }
        compute128_tt(As + p*kAOff, Bst + p*kAOff, wm, wn, g, t, acc);
        if (i+1 < nk) { stA128(As + (1-p)*kAOff, va); stA128(Bst + (1-p)*kAOff, vb); }
        __syncthreads();
    }
    const int row0 = qt*128, col0 = kt*128;
    #pragma unroll
    for (int im = 0; im < 4; im++)
        #pragma unroll
        for (int jn = 0; jn < 4; jn++) {
            int r0 = row0 + wm + im*16 + g;
            int c0 = col0 + wn + jn*8 + 2*t;
            #pragma unroll
            for (int hh = 0; hh < 2; hh++) {
                int qi = r0 + hh*8;
                float v0 = acc[im][jn][hh*2+0]*kScale;
                float v1 = acc[im][jn][hh*2+1]*kScale;
                if (c0   > qi) v0 = -1e9f;
                if (c0+1 > qi) v1 = -1e9f;
                g_scores[((size_t)h*kT + qi)*kT + c0]     = v0;
                g_scores[((size_t)h*kT + qi)*kT + c0 + 1] = v1;
            }
        }
}

// ---------------- row softmax (zero-fill to 128-tile boundary) ----------------
__global__ void softmax_kernel() {
    const int q = blockIdx.x, h = blockIdx.y, tid = threadIdx.x;
    float* row = g_scores + ((size_t)h*kT + q)*kT;
    const int tend = ((q >> 7) + 1) << 7;
    __shared__ float sh[256];
    float lmax = -3.4e38f;
    for (int k = tid; k <= q; k += 256) lmax = fmaxf(lmax, row[k]);
    sh[tid] = lmax; __syncthreads();
    for (int s = 128; s > 0; s >>= 1) { if (tid < s) sh[tid] = fmaxf(sh[tid], sh[tid+s]); __syncthreads(); }
    float m = sh[0]; __syncthreads();
    float lsum = 0.f;
    for (int k = tid; k <= q; k += 256) { float e = __expf(row[k]-m); row[k] = e; lsum += e; }
    sh[tid] = lsum; __syncthreads();
    for (int s = 128; s > 0; s >>= 1) { if (tid < s) sh[tid] += sh[tid+s]; __syncthreads(); }
    float inv = 1.f/sh[0];
    for (int k = tid; k < tend; k += 256) row[k] = (k <= q) ? row[k]*inv : 0.f;
}

// ---------------- PV: O_h = P V_h  (causal-trimmed K; N = 128 = kHD) ----------------
__global__ void __launch_bounds__(256) pv_kernel() {
    const int qt = blockIdx.x, h = blockIdx.y;
    extern __shared__ unsigned smem[];
    unsigned* As = smem;
    unsigned* Bs = smem + 2*kAOff;
    const int row0 = qt*128;
    const int Kdim = (qt + 1)*128;
    const float* A = g_scores + ((size_t)h*kT + row0)*kT;
    const float* B = g_qkv + kNH*kHD + kNKV*kHD + (h >> 2)*kHD;
    const int lane = threadIdx.x & 31, warp = threadIdx.x >> 5;
    const int wm = (warp & 1)*64, wn = (warp >> 1)*32;
    const int g = lane >> 2, t = lane & 3;
    float acc[4][4][4] = {};
    float4 va[4], vb[4];
    ldA128(A, kT, 0, va); ldB128(B, kQKV, 0, vb);
    stA128(As, va); stB128(Bs, vb);
    __syncthreads();
    const int nk = Kdim >> 5;
    for (int i = 0; i < nk; i++) {
        int p = i & 1;
        if (i+1 < nk) { ldA128(A, kT, (i+1)*32, va); ldB128(B, kQKV, (i+1)*32, vb); }
        compute128(As + p*kAOff, Bs + p*kBOff, wm, wn, g, t, acc);
        if (i+1 < nk) { stA128(As + (1-p)*kAOff, va); stB128(Bs + (1-p)*kBOff, vb); }
        __syncthreads();
    }
    #pragma unroll
    for (int im = 0; im < 4; im++)
        #pragma unroll
        for (int jn = 0; jn < 4; jn++) {
            int r0 = row0 + wm + im*16 + g;
            int c0 = wn + jn*8 + 2*t;
            #pragma unroll
            for (int hh = 0; hh < 2; hh++) {
                int rr = r0 + hh*8;
                g_attn[(size_t)rr*kH + h*kHD + c0]     = acc[im][jn][hh*2+0];
                g_attn[(size_t)rr*kH + h*kHD + c0 + 1] = acc[im][jn][hh*2+1];
            }
        }
}

// ---------------- router ----------------
__global__ void router_kernel(const float* __restrict__ gate_w) {
    const int t = blockIdx.x, tid = threadIdx.x;
    const float* hp = g_h2 + (size_t)t*kH;
    float acc[kE] = {};
    for (int k = tid; k < kH; k += 256) {
        float hv = hp[k];
        const float* gw = gate_w + (size_t)k*kE;
        #pragma unroll
        for (int e = 0; e < kE; e++) acc[e] += hv*gw[e];
    }
    __shared__ float sh[kE][256];
    #pragma unroll
    for (int e = 0; e < kE; e++) sh[e][tid] = acc[e];
    __syncthreads();
    for (int s = 128; s > 0; s >>= 1) {
        if (tid < s) {
            #pragma unroll
            for (int e = 0; e < kE; e++) sh[e][tid] += sh[e][tid+s];
        }
        __syncthreads();
    }
    if (tid == 0) {
        float l[kE], mx = -3.4e38f;
        #pragma unroll
        for (int e = 0; e < kE; e++) { l[e] = sh[e][0]; mx = fmaxf(mx, l[e]); }
        float sum = 0.f;
        #pragma unroll
        for (int e = 0; e < kE; e++) { l[e] = __expf(l[e]-mx); sum += l[e]; }
        float isum = 1.f/sum;
        float best = -1.f, second = -1.f; int bi = 0, si = 0;
        #pragma unroll
        for (int e = 0; e < kE; e++) {
            float p = l[e]*isum;
            if (p > best) { second = best; si = bi; best = p; bi = e; }
            else if (p > second) { second = p; si = e; }
        }
        float denom = 1.f/(best + second);
        g_topi[t*2]   = bi; g_topw[t*2]   = best*denom;
        g_topi[t*2+1] = si; g_topw[t*2+1] = second*denom;
        atomicAdd(&g_cnt[bi], 1);
        atomicAdd(&g_cnt[si], 1);
    }
}

__global__ void moe_init_kernel() {
    int i = blockIdx.x*256 + threadIdx.x;
    if (i < kE) { g_cnt[i] = 0; }
    if (i < kSlots) g_tok[i] = -1;
}

__global__ void moe_setup_kernel() {
    int off = 0, tile = 0;
    for (int e = 0; e < kE; e++) {
        g_cursor[e] = off;
        int seg = ((g_cnt[e] + 127)/128)*128;
        for (int i = 0; i < seg/128; i++) g_tile_e[tile++] = e;
        off += seg;
    }
    g_ntiles = tile;
}

__global__ void moe_scatter_kernel() {
    int t = blockIdx.x*256 + threadIdx.x;
    if (t >= kT) return;
    #pragma unroll
    for (int k = 0; k < 2; k++) {
        int e = g_topi[t*2+k];
        int pos = atomicAdd(&g_cursor[e], 1);
        g_tok[pos] = t;
        g_wt[pos]  = g_topw[t*2+k];
        g_slot_of[t*2+k] = pos;
    }
}

// ---------------- MoE GEMM 1: gate_up (gathered rows) ----------------
__global__ void __launch_bounds__(256) moe_gu_kernel(const float* __restrict__ w_gate_up) {
    const int tile = blockIdx.x;
    if (tile >= g_ntiles) return;
    extern __shared__ unsigned smem[];
    unsigned* As = smem;
    unsigned* Bs = smem + 2*kAOff;
    __shared__ int rows[128];
    const int tid = threadIdx.x;
    if (tid < 128) rows[tid] = g_tok[tile*128 + tid];
    __syncthreads();
    const int e = g_tile_e[tile];
    const int col0 = blockIdx.y*128;
    const float* B = w_gate_up + (size_t)e*kH*2*kI + col0;
    const int lane = tid & 31, warp = tid >> 5;
    const int wm = (warp & 1)*64, wn = (warp >> 1)*32;
    const int g = lane >> 2, t = lane & 3;
    float acc[4][4][4] = {};
    float4 va[4], vb[4];
    ldA128_gather(g_h2, kH, rows, 0, va); ldB128(B, 2*kI, 0, vb);
    stA128(As, va); stB128(Bs, vb);
    __syncthreads();
    const int nk = kH >> 5;
    for (int i = 0; i < nk; i++) {
        int p = i & 1;
        if (i+1 < nk) { ldA128_gather(g_h2, kH, rows, (i+1)*32, va); ldB128(B, 2*kI, (i+1)*32, vb); }
        compute128(As + p*kAOff, Bs + p*kBOff, wm, wn, g, t, acc);
        if (i+1 < nk) { stA128(As + (1-p)*kAOff, va); stB128(Bs + (1-p)*kBOff, vb); }
        __syncthreads();
    }
    #pragma unroll
    for (int im = 0; im < 4; im++)
        #pragma unroll
        for (int jn = 0; jn < 4; jn++) {
            int r0 = wm + im*16 + g;
            int c0 = col0 + wn + jn*8 + 2*t;
            #pragma unroll
            for (int hh = 0; hh < 2; hh++) {
                int slot = tile*128 + r0 + hh*8;
                g_gu[(size_t)slot*2*kI + c0]     = acc[im][jn][hh*2+0];
                g_gu[(size_t)slot*2*kI + c0 + 1] = acc[im][jn][hh*2+1];
            }
        }
}

__global__ void silu_kernel() {
    int idx = blockIdx.x*256 + threadIdx.x;
    int slot = idx / kI, j = idx % kI;
    if (slot >= g_ntiles*128) return;
    float g = g_gu[(size_t)slot*2*kI + j];
    float u = g_gu[(size_t)slot*2*kI + kI + j];
    g_act[idx] = (g / (1.f + __expf(-g))) * u;
}

// ---------------- MoE GEMM 2: down ----------------
__global__ void __launch_bounds__(256) moe_down_kernel(const float* __restrict__ w_down) {
    const int tile = blockIdx.x;
    if (tile >= g_ntiles) return;
    extern __shared__ unsigned smem[];
    unsigned* As = smem;
    unsigned* Bs = smem + 2*kAOff;
    const int e = g_tile_e[tile];
    const int col0 = blockIdx.y*128;
    const float* A = g_act + (size_t)tile*128*kI;
    const float* B = w_down + (size_t)e*kI*kH + col0;
    const int lane = threadIdx.x & 31, warp = threadIdx.x >> 5;
    const int wm = (warp & 1)*64, wn = (warp >> 1)*32;
    const int g = lane >> 2, t = lane & 3;
    float acc[4][4][4] = {};
    float4 va[4], vb[4];
    ldA128(A, kI, 0, va); ldB128(B, kH, 0, vb);
    stA128(As, va); stB128(Bs, vb);
    __syncthreads();
    const int nk = kI >> 5;
    for (int i = 0; i < nk; i++) {
        int p = i & 1;
        if (i+1 < nk) { ldA128(A, kI, (i+1)*32, va); ldB128(B, kH, (i+1)*32, vb); }
        compute128(As + p*kAOff, Bs + p*kBOff, wm, wn, g, t, acc);
        if (i+1 < nk) { stA128(As + (1-p)*kAOff, va); stB128(Bs + (1-p)*kBOff, vb); }
        __syncthreads();
    }
    #pragma unroll
    for (int im = 0; im < 4; im++)
        #pragma unroll
        for (int jn = 0; jn < 4; jn++) {
            int r0 = wm + im*16 + g;
            int c0 = col0 + wn + jn*8 + 2*t;
            #pragma unroll
            for (int hh = 0; hh < 2; hh++) {
                int slot = tile*128 + r0 + hh*8;
                g_ds[(size_t)slot*kH + c0]     = acc[im][jn][hh*2+0];
                g_ds[(size_t)slot*kH + c0 + 1] = acc[im][jn][hh*2+1];
            }
        }
}

__global__ void combine_kernel(float* __restrict__ out) {
    const int t = blockIdx.x;
    const int s0 = g_slot_of[t*2], s1 = g_slot_of[t*2+1];
    const float w0 = g_wt[s0], w1 = g_wt[s1];
    for (int j = threadIdx.x; j < kH; j += 256)
        out[(size_t)t*kH + j] = w0*g_ds[(size_t)s0*kH + j] + w1*g_ds[(size_t)s1*kH + j];
}

// ---------------- launcher ----------------
extern "C" void kernel_launch(void* const* d_in, const int* in_sizes, int n_in,
                              void* d_out, int out_size) {
    const int*   positions = (const int*)  d_in[0];
    const float* hidden    = (const float*)d_in[1];
    const float* residual  = (const float*)d_in[2];
    const float* w_qkv     = (const float*)d_in[3];
    const float* w_o       = (const float*)d_in[4];
    const float* q_norm_w  = (const float*)d_in[5];
    const float* k_norm_w  = (const float*)d_in[6];
    const float* ln1_w     = (const float*)d_in[7];
    const float* ln2_w     = (const float*)d_in[8];
    const float* gate_w    = (const float*)d_in[9];
    const float* w_gate_up = (const float*)d_in[10];
    const float* w_down    = (const float*)d_in[11];
    float* out = (float*)d_out;
    float* res = out + (size_t)kT*kH;

    float* d_h1;   cudaGetSymbolAddress((void**)&d_h1,   g_h1);
    float* d_qkv;  cudaGetSymbolAddress((void**)&d_qkv,  g_qkv);
    float* d_attn; cudaGetSymbolAddress((void**)&d_attn, g_attn);
    float* d_h2;   cudaGetSymbolAddress((void**)&d_h2,   g_h2);

    cudaFuncSetAttribute(gemm_plain_kernel, cudaFuncAttributeMaxDynamicSharedMemorySize, (int)kPlainSmem);
    cudaFuncSetAttribute(scores_kernel,     cudaFuncAttributeMaxDynamicSharedMemorySize, (int)kTTSmem);
    cudaFuncSetAttribute(pv_kernel,         cudaFuncAttributeMaxDynamicSharedMemorySize, (int)kPlainSmem);
    cudaFuncSetAttribute(moe_gu_kernel,     cudaFuncAttributeMaxDynamicSharedMemorySize, (int)kPlainSmem);
    cudaFuncSetAttribute(moe_down_kernel,   cudaFuncAttributeMaxDynamicSharedMemorySize, (int)kPlainSmem);

    add_rms_kernel<<<kT, 256>>>(hidden, residual, ln1_w, res, d_h1);
    gemm_plain_kernel<<<dim3(kT/128, kQKV/128), 256, kPlainSmem>>>(d_h1, kH, w_qkv, kQKV, d_qkv, kQKV, kH, nullptr);
    rope_kernel<<<dim3(kT, kNH + kNKV), 128>>>(positions, q_norm_w, k_norm_w);
    scores_kernel<<<dim3(kT/128, kT/128, kNH), 256, kTTSmem>>>();
    softmax_kernel<<<dim3(kT, kNH), 256>>>();
    pv_kernel<<<dim3(kT/128, kNH), 256, kPlainSmem>>>();
    gemm_plain_kernel<<<dim3(kT/128, kH/128), 256, kPlainSmem>>>(d_attn, kH, w_o, kH, res, kH, kH, res);
    add_rms_kernel<<<kT, 256>>>(res, nullptr, ln2_w, nullptr, d_h2);
    moe_init_kernel<<<(kSlots + 255)/256, 256>>>();
    router_kernel<<<kT, 256>>>(gate_w);
    moe_setup_kernel<<<1, 1>>>();
    moe_scatter_kernel<<<(kT + 255)/256, 256>>>();
    moe_gu_kernel<<<dim3(kTiles, 2*kI/128), 256, kPlainSmem>>>(w_gate_up);
    silu_kernel<<<(kSlots*kI)/256, 256>>>();
    moe_down_kernel<<<dim3(kTiles, kH/128), 256, kPlainSmem>>>(w_down);
    combine_kernel<<<kT, 256>>>(out);
}

// round 4
// speedup vs baseline: 2.2476x; 1.0104x over previous
#include <cuda_runtime.h>
#include <math.h>

// ---------------- problem constants ----------------
constexpr int kT   = 1024;
constexpr int kH   = 2048;
constexpr int kNH  = 16;
constexpr int kNKV = 4;
constexpr int kHD  = 128;
constexpr int kE   = 8;
constexpr int kI   = 768;
constexpr int kQKV = kNH*kHD + 2*kNKV*kHD;   // 3072
constexpr float kEPS = 1e-6f;
constexpr float kScale = 0.08838834764831845f;

constexpr int kSlots = 3072;
constexpr int kTiles = kSlots / 128; // 24
constexpr int kStages = 3;

// ---------------- scratch ----------------
__device__ float g_h1[kT*kH];
__device__ float g_qkv[kT*kQKV];
__device__ float g_scores[(size_t)kNH*kT*kT];
__device__ float g_attn[kT*kH];
__device__ float g_h2[(kT+1)*kH];      // +1 zero row for gather padding
__device__ float g_h2f[kT*kH];         // full-precision (router)
__device__ float g_gu[(size_t)kSlots*2*kI];
__device__ float g_act[(size_t)kSlots*kI];
__device__ float g_ds[(size_t)kSlots*kH];
__device__ int   g_tok[kSlots];
__device__ float g_wt[kSlots];
__device__ int   g_slot_of[kT*2];
__device__ int   g_topi[kT*2];
__device__ float g_topw[kT*2];
__device__ int   g_cnt[kE];
__device__ int   g_cursor[kE];
__device__ int   g_tile_e[kTiles];
__device__ int   g_ntiles;
// pre-rounded (tf32) weights
__device__ float g_wqkv_t[kH*kQKV];
__device__ float g_wo_t[kH*kH];
__device__ float g_wgu_t[(size_t)kE*kH*2*kI];
__device__ float g_wdn_t[(size_t)kE*kI*kH];

// ---------------- tf32 / mma / cp.async helpers ----------------
__device__ __forceinline__ unsigned f2tf(float x) {
    unsigned r; asm("cvt.rna.tf32.f32 %0, %1;" : "=r"(r) : "f"(x)); return r;
}
__device__ __forceinline__ float rtf(float x) { return __uint_as_float(f2tf(x)); }

__device__ __forceinline__ void mma_tf32(float c[4],
                                         unsigned a0, unsigned a1, unsigned a2, unsigned a3,
                                         unsigned b0, unsigned b1) {
    asm volatile("mma.sync.aligned.m16n8k8.row.col.f32.tf32.tf32.f32 "
                 "{%0,%1,%2,%3}, {%4,%5,%6,%7}, {%8,%9}, {%0,%1,%2,%3};"
                 : "+f"(c[0]), "+f"(c[1]), "+f"(c[2]), "+f"(c[3])
                 : "r"(a0), "r"(a1), "r"(a2), "r"(a3), "r"(b0), "r"(b1));
}
__device__ __forceinline__ unsigned sptr(const void* p) {
    return (unsigned)__cvta_generic_to_shared(p);
}
__device__ __forceinline__ void cp16(unsigned dst, const void* src) {
    asm volatile("cp.async.cg.shared.global [%0], [%1], 16;" :: "r"(dst), "l"(src));
}
__device__ __forceinline__ void cp_commit() { asm volatile("cp.async.commit_group;"); }
__device__ __forceinline__ void cp_wait1()  { asm volatile("cp.async.wait_group 1;"); }
__device__ __forceinline__ void ldsm4(unsigned& r0, unsigned& r1, unsigned& r2, unsigned& r3,
                                      unsigned addr) {
    asm volatile("ldmatrix.sync.aligned.m8n8.x4.shared.b16 {%0,%1,%2,%3}, [%4];"
                 : "=r"(r0), "=r"(r1), "=r"(r2), "=r"(r3) : "r"(addr));
}

constexpr int kSA = 36;          // A/n-major row stride (words); ldsm conflict-free
constexpr int kSB = 136;         // B row-major stride (words); 8t+g conflict-free
constexpr int kABuf = 128*kSA;   // words per A stage (18432 B)
constexpr int kBBuf = 32*kSB;    // words per B stage (17408 B)
constexpr size_t kPlainSmem = (size_t)kStages*(kABuf + kBBuf)*4; // 107520
constexpr size_t kTTSmem    = (size_t)kStages*2*kABuf*4;         // 110592

// per-lane ldmatrix A-base byte offset (within an A stage buffer), for m-tile base wm
__device__ __forceinline__ unsigned a_base_off(int wm, int lane) {
    int sub = lane >> 3, lr = lane & 7;
    int r = wm + (sub & 1)*8 + lr;
    int c = (sub >> 1)*4;
    return 4u*(r*kSA + c);
}
// per-lane ldmatrix B-base (n-major layout), pair p covers jn=2p,2p+1 at warp col wn
__device__ __forceinline__ unsigned b_base_off(int wn, int p, int lane) {
    int sub = lane >> 3, lr = lane & 7;
    int r = wn + p*16 + (sub >> 1)*8 + lr;
    int c = (sub & 1)*4;
    return 4u*(r*kSA + c);
}

// compute one staged chunk, plain B (row-major [32][kSB])
__device__ __forceinline__ void compute_plain(unsigned aBase, const unsigned* __restrict__ Bc,
                                              int wn, int g, int t, float acc[4][4][4]) {
    #pragma unroll
    for (int kk = 0; kk < 32; kk += 8) {
        unsigned a[4][4], b[4][2];
        #pragma unroll
        for (int im = 0; im < 4; im++)
            ldsm4(a[im][0], a[im][1], a[im][2], a[im][3], aBase + 4u*(im*16*kSA + kk));
        #pragma unroll
        for (int jn = 0; jn < 4; jn++) {
            b[jn][0] = Bc[(kk+t)*kSB   + wn + jn*8 + g];
            b[jn][1] = Bc[(kk+t+4)*kSB + wn + jn*8 + g];
        }
        #pragma unroll
        for (int im = 0; im < 4; im++)
            #pragma unroll
            for (int jn = 0; jn < 4; jn++)
                mma_tf32(acc[im][jn], a[im][0], a[im][1], a[im][2], a[im][3],
                         b[jn][0], b[jn][1]);
    }
}
// compute one staged chunk, B n-major (ldmatrix both sides)
__device__ __forceinline__ void compute_tt(unsigned aBase, unsigned bBase0, unsigned bBase1,
                                           float acc[4][4][4]) {
    #pragma unroll
    for (int kk = 0; kk < 32; kk += 8) {
        unsigned a[4][4], b[4][2];
        #pragma unroll
        for (int im = 0; im < 4; im++)
            ldsm4(a[im][0], a[im][1], a[im][2], a[im][3], aBase + 4u*(im*16*kSA + kk));
        ldsm4(b[0][0], b[0][1], b[1][0], b[1][1], bBase0 + 4u*kk);
        ldsm4(b[2][0], b[2][1], b[3][0], b[3][1], bBase1 + 4u*kk);
        #pragma unroll
        for (int im = 0; im < 4; im++)
            #pragma unroll
            for (int jn = 0; jn < 4; jn++)
                mma_tf32(acc[im][jn], a[im][0], a[im][1], a[im][2], a[im][3],
                         b[jn][0], b[jn][1]);
    }
}

// ---------------- tf32 pre-round ----------------
__global__ void cvt_kernel(const float* __restrict__ src, float* __restrict__ dst, int n4) {
    int i = blockIdx.x*256 + threadIdx.x;
    if (i >= n4) return;
    float4 v = reinterpret_cast<const float4*>(src)[i];
    v.x = rtf(v.x); v.y = rtf(v.y); v.z = rtf(v.z); v.w = rtf(v.w);
    reinterpret_cast<float4*>(dst)[i] = v;
}

// ---------------- fused add + RMSNorm (h_out tf32-rounded; h_full optional) ----------------
__global__ void add_rms_kernel(const float* __restrict__ x, const float* __restrict__ r,
                               const float* __restrict__ w, float* __restrict__ res_out,
                               float* __restrict__ h_out, float* __restrict__ h_full) {
    const int t = blockIdx.x, tid = threadIdx.x;
    const float* xp = x + (size_t)t*kH;
    const float* rp = r ? r + (size_t)t*kH : nullptr;
    float v[8]; float ss = 0.f;
    #pragma unroll
    for (int i = 0; i < 8; i++) {
        int idx = tid + i*256;
        float val = xp[idx];
        if (rp) val += rp[idx];
        v[i] = val; ss += val*val;
    }
    __shared__ float sh[256];
    sh[tid] = ss; __syncthreads();
    for (int s = 128; s > 0; s >>= 1) { if (tid < s) sh[tid] += sh[tid+s]; __syncthreads(); }
    float scale = rsqrtf(sh[0]/(float)kH + kEPS);
    #pragma unroll
    for (int i = 0; i < 8; i++) {
        int idx = tid + i*256;
        if (res_out) res_out[(size_t)t*kH + idx] = v[i];
        float hv = v[i]*scale*w[idx];
        h_out[(size_t)t*kH + idx] = rtf(hv);
        if (h_full) h_full[(size_t)t*kH + idx] = hv;
    }
}

// ---------------- generic 128x128 GEMM, cp.async 3-stage ----------------
__global__ void __launch_bounds__(256, 2)
gemm_plain_kernel(const float* __restrict__ A, int lda,
                  const float* __restrict__ B, int ldb,
                  float* __restrict__ C, int ldc, int Kdim,
                  const float* __restrict__ addsrc) {
    extern __shared__ unsigned smem[];
    unsigned* As = smem;
    unsigned* Bs = smem + kStages*kABuf;
    const int row0 = blockIdx.x*128, col0 = blockIdx.y*128;
    const int tid = threadIdx.x, lane = tid & 31, warp = tid >> 5;
    const int wm = (warp & 1)*64, wn = (warp >> 1)*32;
    const int g = lane >> 2, t = lane & 3;
    const float* Ab = A + (size_t)row0*lda;
    const float* Bb = B + col0;
    const int nk = Kdim >> 5;

    auto issue = [&](int s) {
        unsigned* Ad = As + (s % kStages)*kABuf;
        unsigned* Bd = Bs + (s % kStages)*kBBuf;
        int kk0 = s*32;
        #pragma unroll
        for (int q = 0; q < 4; q++) {
            int e = tid + q*256;
            int m = e >> 3, k4 = e & 7;
            cp16(sptr(Ad + m*kSA + k4*4), Ab + (size_t)m*lda + kk0 + k4*4);
        }
        #pragma unroll
        for (int q = 0; q < 4; q++) {
            int e = tid + q*256;
            int k = e >> 5, n16 = e & 31;
            cp16(sptr(Bd + k*kSB + n16*4), Bb + (size_t)(kk0+k)*ldb + n16*4);
        }
        cp_commit();
    };
    for (int s = 0; s < kStages-1; s++) { if (s < nk) issue(s); else cp_commit(); }

    const unsigned aOff = a_base_off(wm, lane);
    float acc[4][4][4] = {};
    for (int i = 0; i < nk; i++) {
        cp_wait1();
        __syncthreads();
        int p = i % kStages;
        compute_plain(sptr(As + p*kABuf) + aOff, Bs + p*kBBuf, wn, g, t, acc);
        __syncthreads();
        int s = i + kStages - 1;
        if (s < nk) issue(s); else cp_commit();
    }
    #pragma unroll
    for (int im = 0; im < 4; im++)
        #pragma unroll
        for (int jn = 0; jn < 4; jn++) {
            int r0 = row0 + wm + im*16 + g;
            int c0 = col0 + wn + jn*8 + 2*t;
            #pragma unroll
            for (int hh = 0; hh < 2; hh++) {
                int rr = r0 + hh*8;
                float v0 = acc[im][jn][hh*2+0], v1 = acc[im][jn][hh*2+1];
                if (addsrc) {
                    v0 += addsrc[(size_t)rr*ldc + c0];
                    v1 += addsrc[(size_t)rr*ldc + c0 + 1];
                }
                C[(size_t)rr*ldc + c0]     = v0;
                C[(size_t)rr*ldc + c0 + 1] = v1;
            }
        }
}

// ---------------- QK-RMSNorm + RoPE + v-round (in place on g_qkv) ----------------
__global__ void rope_kernel(const int* __restrict__ positions,
                            const float* __restrict__ q_norm_w,
                            const float* __restrict__ k_norm_w) {
    const int t = blockIdx.x, hh = blockIdx.y, lane = threadIdx.x; // 128 threads
    if (hh >= kNH + kNKV) { // v heads: round only
        int vh = hh - kNH - kNKV;
        float* ptr = g_qkv + (size_t)t*kQKV + (kNH + kNKV)*kHD + vh*kHD;
        ptr[lane] = rtf(ptr[lane]);
        return;
    }
    float* ptr = g_qkv + (size_t)t*kQKV + (hh < kNH ? hh*kHD : kNH*kHD + (hh-kNH)*kHD);
    const float* nw = (hh < kNH) ? q_norm_w : k_norm_w;
    float v = ptr[lane];
    __shared__ float sred[128];
    sred[lane] = v*v; __syncthreads();
    for (int s = 64; s > 0; s >>= 1) { if (lane < s) sred[lane] += sred[lane+s]; __syncthreads(); }
    float scale = rsqrtf(sred[0]/(float)kHD + kEPS);
    float xn = v*scale*nw[lane];
    __shared__ float sh[128];
    sh[lane] = xn; __syncthreads();
    int j = lane & 63;
    double inv = exp(-(double)j/64.0 * log(1.0e6));
    double ang = (double)positions[t] * inv;
    float c = (float)cos(ang), s = (float)sin(ang);
    float outv;
    if (lane < 64) outv = sh[lane]*c - sh[lane+64]*s;
    else           outv = sh[lane]*c + sh[lane-64]*s;
    ptr[lane] = rtf(outv);
}

// ---------------- attention scores: Q K^T (both operands n-major rows) ----------------
__global__ void __launch_bounds__(256, 2) scores_kernel() {
    const int qt = blockIdx.x, kt = blockIdx.y, h = blockIdx.z;
    if (kt > qt) return;
    extern __shared__ unsigned smem[];
    unsigned* As  = smem;
    unsigned* Bst = smem + kStages*kABuf;
    const float* Q  = g_qkv + (size_t)qt*128*kQKV + h*kHD;
    const float* Kp = g_qkv + (size_t)kt*128*kQKV + kNH*kHD + (h >> 2)*kHD;
    const int tid = threadIdx.x, lane = tid & 31, warp = tid >> 5;
    const int wm = (warp & 1)*64, wn = (warp >> 1)*32;
    const int g = lane >> 2, t = lane & 3;
    const int nk = kHD >> 5;  // 4

    auto issue = [&](int s) {
        unsigned* Ad = As  + (s % kStages)*kABuf;
        unsigned* Bd = Bst + (s % kStages)*kABuf;
        int kk0 = s*32;
        #pragma unroll
        for (int q = 0; q < 4; q++) {
            int e = tid + q*256;
            int m = e >> 3, k4 = e & 7;
            cp16(sptr(Ad + m*kSA + k4*4), Q  + (size_t)m*kQKV + kk0 + k4*4);
            cp16(sptr(Bd + m*kSA + k4*4), Kp + (size_t)m*kQKV + kk0 + k4*4);
        }
        cp_commit();
    };
    for (int s = 0; s < kStages-1; s++) { if (s < nk) issue(s); else cp_commit(); }

    const unsigned aOff  = a_base_off(wm, lane);
    const unsigned bOff0 = b_base_off(wn, 0, lane);
    const unsigned bOff1 = b_base_off(wn, 1, lane);
    float acc[4][4][4] = {};
    for (int i = 0; i < nk; i++) {
        cp_wait1();
        __syncthreads();
        int p = i % kStages;
        unsigned ab = sptr(As  + p*kABuf);
        unsigned bb = sptr(Bst + p*kABuf);
        compute_tt(ab + aOff, bb + bOff0, bb + bOff1, acc);
        __syncthreads();
        int s = i + kStages - 1;
        if (s < nk) issue(s); else cp_commit();
    }
    const int row0 = qt*128, col0 = kt*128;
    #pragma unroll
    for (int im = 0; im < 4; im++)
        #pragma unroll
        for (int jn = 0; jn < 4; jn++) {
            int r0 = row0 + wm + im*16 + g;
            int c0 = col0 + wn + jn*8 + 2*t;
            #pragma unroll
            for (int hh = 0; hh < 2; hh++) {
                int qi = r0 + hh*8;
                float v0 = acc[im][jn][hh*2+0]*kScale;
                float v1 = acc[im][jn][hh*2+1]*kScale;
                if (c0   > qi) v0 = -1e9f;
                if (c0+1 > qi) v1 = -1e9f;
                g_scores[((size_t)h*kT + qi)*kT + c0]     = v0;
                g_scores[((size_t)h*kT + qi)*kT + c0 + 1] = v1;
            }
        }
}

// ---------------- row softmax (rounded probs, zero-fill to 128 boundary) ----------------
__global__ void softmax_kernel() {
    const int q = blockIdx.x, h = blockIdx.y, tid = threadIdx.x;
    float* row = g_scores + ((size_t)h*kT + q)*kT;
    const int tend = ((q >> 7) + 1) << 7;
    __shared__ float sh[256];
    float lmax = -3.4e38f;
    for (int k = tid; k <= q; k += 256) lmax = fmaxf(lmax, row[k]);
    sh[tid] = lmax; __syncthreads();
    for (int s = 128; s > 0; s >>= 1) { if (tid < s) sh[tid] = fmaxf(sh[tid], sh[tid+s]); __syncthreads(); }
    float m = sh[0]; __syncthreads();
    float lsum = 0.f;
    for (int k = tid; k <= q; k += 256) { float e = __expf(row[k]-m); row[k] = e; lsum += e; }
    sh[tid] = lsum; __syncthreads();
    for (int s = 128; s > 0; s >>= 1) { if (tid < s) sh[tid] += sh[tid+s]; __syncthreads(); }
    float inv = 1.f/sh[0];
    for (int k = tid; k < tend; k += 256) row[k] = (k <= q) ? rtf(row[k]*inv) : 0.f;
}

// ---------------- PV: O_h = P V_h (causal-trimmed, rounded output) ----------------
__global__ void __launch_bounds__(256, 2) pv_kernel() {
    const int qt = blockIdx.x, h = blockIdx.y;
    extern __shared__ unsigned smem[];
    unsigned* As = smem;
    unsigned* Bs = smem + kStages*kABuf;
    const int row0 = qt*128;
    const int Kdim = (qt + 1)*128;
    const float* A = g_scores + ((size_t)h*kT + row0)*kT;
    const float* B = g_qkv + (kNH + kNKV)*kHD + (h >> 2)*kHD;
    const int tid = threadIdx.x, lane = tid & 31, warp = tid >> 5;
    const int wm = (warp & 1)*64, wn = (warp >> 1)*32;
    const int g = lane >> 2, t = lane & 3;
    const int nk = Kdim >> 5;

    auto issue = [&](int s) {
        unsigned* Ad = As + (s % kStages)*kABuf;
        unsigned* Bd = Bs + (s % kStages)*kBBuf;
        int kk0 = s*32;
        #pragma unroll
        for (int q = 0; q < 4; q++) {
            int e = tid + q*256;
            int m = e >> 3, k4 = e & 7;
            cp16(sptr(Ad + m*kSA + k4*4), A + (size_t)m*kT + kk0 + k4*4);
        }
        #pragma unroll
        for (int q = 0; q < 4; q++) {
            int e = tid + q*256;
            int k = e >> 5, n16 = e & 31;
            cp16(sptr(Bd + k*kSB + n16*4), B + (size_t)(kk0+k)*kQKV + n16*4);
        }
        cp_commit();
    };
    for (int s = 0; s < kStages-1; s++) { if (s < nk) issue(s); else cp_commit(); }

    const unsigned aOff = a_base_off(wm, lane);
    float acc[4][4][4] = {};
    for (int i = 0; i < nk; i++) {
        cp_wait1();
        __syncthreads();
        int p = i % kStages;
        compute_plain(sptr(As + p*kABuf) + aOff, Bs + p*kBBuf, wn, g, t, acc);
        __syncthreads();
        int s = i + kStages - 1;
        if (s < nk) issue(s); else cp_commit();
    }
    #pragma unroll
    for (int im = 0; im < 4; im++)
        #pragma unroll
        for (int jn = 0; jn < 4; jn++) {
            int r0 = row0 + wm + im*16 + g;
            int c0 = wn + jn*8 + 2*t;
            #pragma unroll
            for (int hh = 0; hh < 2; hh++) {
                int rr = r0 + hh*8;
                g_attn[(size_t)rr*kH + h*kHD + c0]     = rtf(acc[im][jn][hh*2+0]);
                g_attn[(size_t)rr*kH + h*kHD + c0 + 1] = rtf(acc[im][jn][hh*2+1]);
            }
        }
}

// ---------------- router (full-precision h2) ----------------
__global__ void router_kernel(const float* __restrict__ gate_w) {
    const int t = blockIdx.x, tid = threadIdx.x;
    const float* hp = g_h2f + (size_t)t*kH;
    float acc[kE] = {};
    for (int k = tid; k < kH; k += 256) {
        float hv = hp[k];
        const float* gw = gate_w + (size_t)k*kE;
        #pragma unroll
        for (int e = 0; e < kE; e++) acc[e] += hv*gw[e];
    }
    __shared__ float sh[kE][256];
    #pragma unroll
    for (int e = 0; e < kE; e++) sh[e][tid] = acc[e];
    __syncthreads();
    for (int s = 128; s > 0; s >>= 1) {
        if (tid < s) {
            #pragma unroll
            for (int e = 0; e < kE; e++) sh[e][tid] += sh[e][tid+s];
        }
        __syncthreads();
    }
    if (tid == 0) {
        float l[kE], mx = -3.4e38f;
        #pragma unroll
        for (int e = 0; e < kE; e++) { l[e] = sh[e][0]; mx = fmaxf(mx, l[e]); }
        float sum = 0.f;
        #pragma unroll
        for (int e = 0; e < kE; e++) { l[e] = __expf(l[e]-mx); sum += l[e]; }
        float isum = 1.f/sum;
        float best = -1.f, second = -1.f; int bi = 0, si = 0;
        #pragma unroll
        for (int e = 0; e < kE; e++) {
            float p = l[e]*isum;
            if (p > best) { second = best; si = bi; best = p; bi = e; }
            else if (p > second) { second = p; si = e; }
        }
        float denom = 1.f/(best + second);
        g_topi[t*2]   = bi; g_topw[t*2]   = best*denom;
        g_topi[t*2+1] = si; g_topw[t*2+1] = second*denom;
        atomicAdd(&g_cnt[bi], 1);
        atomicAdd(&g_cnt[si], 1);
    }
}

__global__ void moe_init_kernel() {
    int i = blockIdx.x*256 + threadIdx.x;
    if (i < kE) g_cnt[i] = 0;
    if (i < kSlots) g_tok[i] = kT;               // pad -> zero row
    if (i < kH) g_h2[(size_t)kT*kH + i] = 0.f;   // the zero row
}

__global__ void moe_setup_kernel() {
    int off = 0, tile = 0;
    for (int e = 0; e < kE; e++) {
        g_cursor[e] = off;
        int seg = ((g_cnt[e] + 127)/128)*128;
        for (int i = 0; i < seg/128; i++) g_tile_e[tile++] = e;
        off += seg;
    }
    g_ntiles = tile;
}

__global__ void moe_scatter_kernel() {
    int t = blockIdx.x*256 + threadIdx.x;
    if (t >= kT) return;
    #pragma unroll
    for (int k = 0; k < 2; k++) {
        int e = g_topi[t*2+k];
        int pos = atomicAdd(&g_cursor[e], 1);
        g_tok[pos] = t;
        g_wt[pos]  = g_topw[t*2+k];
        g_slot_of[t*2+k] = pos;
    }
}

// ---------------- MoE GEMM 1: gate_up (gathered rows) ----------------
__global__ void __launch_bounds__(256, 2) moe_gu_kernel() {
    const int tile = blockIdx.x;
    if (tile >= g_ntiles) return;
    extern __shared__ unsigned smem[];
    unsigned* As = smem;
    unsigned* Bs = smem + kStages*kABuf;
    __shared__ int rows[128];
    const int tid = threadIdx.x;
    if (tid < 128) rows[tid] = g_tok[tile*128 + tid];
    __syncthreads();
    const int e = g_tile_e[tile];
    const int col0 = blockIdx.y*128;
    const float* Bb = g_wgu_t + (size_t)e*kH*2*kI + col0;
    const int lane = tid & 31, warp = tid >> 5;
    const int wm = (warp & 1)*64, wn = (warp >> 1)*32;
    const int g = lane >> 2, t = lane & 3;
    const int nk = kH >> 5;

    auto issue = [&](int s) {
        unsigned* Ad = As + (s % kStages)*kABuf;
        unsigned* Bd = Bs + (s % kStages)*kBBuf;
        int kk0 = s*32;
        #pragma unroll
        for (int q = 0; q < 4; q++) {
            int ee = tid + q*256;
            int m = ee >> 3, k4 = ee & 7;
            cp16(sptr(Ad + m*kSA + k4*4), g_h2 + (size_t)rows[m]*kH + kk0 + k4*4);
        }
        #pragma unroll
        for (int q = 0; q < 4; q++) {
            int ee = tid + q*256;
            int k = ee >> 5, n16 = ee & 31;
            cp16(sptr(Bd + k*kSB + n16*4), Bb + (size_t)(kk0+k)*(2*kI) + n16*4);
        }
        cp_commit();
    };
    for (int s = 0; s < kStages-1; s++) { if (s < nk) issue(s); else cp_commit(); }

    const unsigned aOff = a_base_off(wm, lane);
    float acc[4][4][4] = {};
    for (int i = 0; i < nk; i++) {
        cp_wait1();
        __syncthreads();
        int p = i % kStages;
        compute_plain(sptr(As + p*kABuf) + aOff, Bs + p*kBBuf, wn, g, t, acc);
        __syncthreads();
        int s = i + kStages - 1;
        if (s < nk) issue(s); else cp_commit();
    }
    #pragma unroll
    for (int im = 0; im < 4; im++)
        #pragma unroll
        for (int jn = 0; jn < 4; jn++) {
            int r0 = wm + im*16 + g;
            int c0 = col0 + wn + jn*8 + 2*t;
            #pragma unroll
            for (int hh = 0; hh < 2; hh++) {
                int slot = tile*128 + r0 + hh*8;
                g_gu[(size_t)slot*2*kI + c0]     = acc[im][jn][hh*2+0];
                g_gu[(size_t)slot*2*kI + c0 + 1] = acc[im][jn][hh*2+1];
            }
        }
}

__global__ void silu_kernel() {
    int idx = blockIdx.x*256 + threadIdx.x;
    int slot = idx / kI, j = idx % kI;
    if (slot >= g_ntiles*128) return;
    float g = g_gu[(size_t)slot*2*kI + j];
    float u = g_gu[(size_t)slot*2*kI + kI + j];
    g_act[idx] = rtf((g / (1.f + __expf(-g))) * u);
}

// ---------------- MoE GEMM 2: down ----------------
__global__ void __launch_bounds__(256, 2) moe_down_kernel() {
    const int tile = blockIdx.x;
    if (tile >= g_ntiles) return;
    extern __shared__ unsigned smem[];
    unsigned* As = smem;
    unsigned* Bs = smem + kStages*kABuf;
    const int e = g_tile_e[tile];
    const int col0 = blockIdx.y*128;
    const float* A  = g_act + (size_t)tile*128*kI;
    const float* Bb = g_wdn_t + (size_t)e*kI*kH + col0;
    const int tid = threadIdx.x, lane = tid & 31, warp = tid >> 5;
    const int wm = (warp & 1)*64, wn = (warp >> 1)*32;
    const int g = lane >> 2, t = lane & 3;
    const int nk = kI >> 5;

    auto issue = [&](int s) {
        unsigned* Ad = As + (s % kStages)*kABuf;
        unsigned* Bd = Bs + (s % kStages)*kBBuf;
        int kk0 = s*32;
        #pragma unroll
        for (int q = 0; q < 4; q++) {
            int ee = tid + q*256;
            int m = ee >> 3, k4 = ee & 7;
            cp16(sptr(Ad + m*kSA + k4*4), A + (size_t)m*kI + kk0 + k4*4);
        }
        #pragma unroll
        for (int q = 0; q < 4; q++) {
            int ee = tid + q*256;
            int k = ee >> 5, n16 = ee & 31;
            cp16(sptr(Bd + k*kSB + n16*4), Bb + (size_t)(kk0+k)*kH + n16*4);
        }
        cp_commit();
    };
    for (int s = 0; s < kStages-1; s++) { if (s < nk) issue(s); else cp_commit(); }

    const unsigned aOff = a_base_off(wm, lane);
    float acc[4][4][4] = {};
    for (int i = 0; i < nk; i++) {
        cp_wait1();
        __syncthreads();
        int p = i % kStages;
        compute_plain(sptr(As + p*kABuf) + aOff, Bs + p*kBBuf, wn, g, t, acc);
        __syncthreads();
        int s = i + kStages - 1;
        if (s < nk) issue(s); else cp_commit();
    }
    #pragma unroll
    for (int im = 0; im < 4; im++)
        #pragma unroll
        for (int jn = 0; jn < 4; jn++) {
            int r0 = wm + im*16 + g;
            int c0 = col0 + wn + jn*8 + 2*t;
            #pragma unroll
            for (int hh = 0; hh < 2; hh++) {
                int slot = tile*128 + r0 + hh*8;
                g_ds[(size_t)slot*kH + c0]     = acc[im][jn][hh*2+0];
                g_ds[(size_t)slot*kH + c0 + 1] = acc[im][jn][hh*2+1];
            }
        }
}

__global__ void combine_kernel(float* __restrict__ out) {
    const int t = blockIdx.x;
    const int s0 = g_slot_of[t*2], s1 = g_slot_of[t*2+1];
    const float w0 = g_wt[s0], w1 = g_wt[s1];
    for (int j = threadIdx.x; j < kH; j += 256)
        out[(size_t)t*kH + j] = w0*g_ds[(size_t)s0*kH + j] + w1*g_ds[(size_t)s1*kH + j];
}

// ---------------- launcher ----------------
extern "C" void kernel_launch(void* const* d_in, const int* in_sizes, int n_in,
                              void* d_out, int out_size) {
    const int*   positions = (const int*)  d_in[0];
    const float* hidden    = (const float*)d_in[1];
    const float* residual  = (const float*)d_in[2];
    const float* w_qkv     = (const float*)d_in[3];
    const float* w_o       = (const float*)d_in[4];
    const float* q_norm_w  = (const float*)d_in[5];
    const float* k_norm_w  = (const float*)d_in[6];
    const float* ln1_w     = (const float*)d_in[7];
    const float* ln2_w     = (const float*)d_in[8];
    const float* gate_w    = (const float*)d_in[9];
    const float* w_gate_up = (const float*)d_in[10];
    const float* w_down    = (const float*)d_in[11];
    float* out = (float*)d_out;
    float* res = out + (size_t)kT*kH;

    float* d_h1;    cudaGetSymbolAddress((void**)&d_h1,    g_h1);
    float* d_qkv;   cudaGetSymbolAddress((void**)&d_qkv,   g_qkv);
    float* d_attn;  cudaGetSymbolAddress((void**)&d_attn,  g_attn);
    float* d_h2;    cudaGetSymbolAddress((void**)&d_h2,    g_h2);
    float* d_h2f;   cudaGetSymbolAddress((void**)&d_h2f,   g_h2f);
    float* d_wqkvt; cudaGetSymbolAddress((void**)&d_wqkvt, g_wqkv_t);
    float* d_wot;   cudaGetSymbolAddress((void**)&d_wot,   g_wo_t);
    float* d_wgut;  cudaGetSymbolAddress((void**)&d_wgut,  g_wgu_t);
    float* d_wdnt;  cudaGetSymbolAddress((void**)&d_wdnt,  g_wdn_t);

    cudaFuncSetAttribute(gemm_plain_kernel, cudaFuncAttributeMaxDynamicSharedMemorySize, (int)kPlainSmem);
    cudaFuncSetAttribute(scores_kernel,     cudaFuncAttributeMaxDynamicSharedMemorySize, (int)kTTSmem);
    cudaFuncSetAttribute(pv_kernel,         cudaFuncAttributeMaxDynamicSharedMemorySize, (int)kPlainSmem);
    cudaFuncSetAttribute(moe_gu_kernel,     cudaFuncAttributeMaxDynamicSharedMemorySize, (int)kPlainSmem);
    cudaFuncSetAttribute(moe_down_kernel,   cudaFuncAttributeMaxDynamicSharedMemorySize, (int)kPlainSmem);

    // weight pre-round (tf32)
    cvt_kernel<<<(kH*kQKV/4 + 255)/256, 256>>>(w_qkv, d_wqkvt, kH*kQKV/4);
    cvt_kernel<<<(kH*kH/4 + 255)/256, 256>>>(w_o, d_wot, kH*kH/4);
    cvt_kernel<<<((int)((size_t)kE*kH*2*kI/4) + 255)/256, 256>>>(w_gate_up, d_wgut, (int)((size_t)kE*kH*2*kI/4));
    cvt_kernel<<<((int)((size_t)kE*kI*kH/4) + 255)/256, 256>>>(w_down, d_wdnt, (int)((size_t)kE*kI*kH/4));

    add_rms_kernel<<<kT, 256>>>(hidden, residual, ln1_w, res, d_h1, nullptr);
    gemm_plain_kernel<<<dim3(kT/128, kQKV/128), 256, kPlainSmem>>>(d_h1, kH, d_wqkvt, kQKV, d_qkv, kQKV, kH, nullptr);
    rope_kernel<<<dim3(kT, kNH + 2*kNKV), 128>>>(positions, q_norm_w, k_norm_w);
    scores_kernel<<<dim3(kT/128, kT/128, kNH), 256, kTTSmem>>>();
    softmax_kernel<<<dim3(kT, kNH), 256>>>();
    pv_kernel<<<dim3(kT/128, kNH), 256, kPlainSmem>>>();
    gemm_plain_kernel<<<dim3(kT/128, kH/128), 256, kPlainSmem>>>(d_attn, kH, d_wot, kH, res, kH, kH, res);
    add_rms_kernel<<<kT, 256>>>(res, nullptr, ln2_w, nullptr, d_h2, d_h2f);
    moe_init_kernel<<<(kSlots + 255)/256, 256>>>();
    router_kernel<<<kT, 256>>>(gate_w);
    moe_setup_kernel<<<1, 1>>>();
    moe_scatter_kernel<<<(kT + 255)/256, 256>>>();
    moe_gu_kernel<<<dim3(kTiles, 2*kI/128), 256, kPlainSmem>>>();
    silu_kernel<<<(kSlots*kI)/256, 256>>>();
    moe_down_kernel<<<dim3(kTiles, kH/128), 256, kPlainSmem>>>();
    combine_kernel<<<kT, 256>>>(out);
}